// round 8
// baseline (speedup 1.0000x reference)
#include <cuda_runtime.h>
#include <cuda_bf16.h>
#include <math.h>
#include <stdint.h>

#define BB 2
#define HH 16
#define SS 2048
#define DH 64
#define DM 1024
#define MM (BB*SS)   // 4096

// ---------------------------------------------------------------------------
// Scratch (device globals)
// ---------------------------------------------------------------------------
__device__ __align__(256) int8_t g_xq1[(size_t)MM*DM];
__device__ __align__(256) int8_t g_xq0[(size_t)MM*DM];
__device__ __align__(256) int8_t g_wq1[(size_t)DM*DM];
__device__ __align__(256) int8_t g_wq0[(size_t)DM*DM];
__device__ __align__(256) int8_t g_wk1[(size_t)DM*DM];
__device__ __align__(256) int8_t g_wk0[(size_t)DM*DM];
__device__ __align__(256) int8_t g_wv1[(size_t)DM*DM];
__device__ __align__(256) int8_t g_wv0[(size_t)DM*DM];
__device__ __align__(256) int8_t g_wo1[(size_t)DM*DM];
__device__ __align__(256) int8_t g_wo0[(size_t)DM*DM];
__device__ __align__(256) int8_t g_cq1[(size_t)MM*DM];
__device__ __align__(256) int8_t g_cq0[(size_t)MM*DM];
// Q,K split bf16 [B,H,S,DH]; V split bf16 transposed [B,H,DH,S]
__device__ __align__(256) __nv_bfloat16 g_qh[(size_t)MM*DM];
__device__ __align__(256) __nv_bfloat16 g_ql[(size_t)MM*DM];
__device__ __align__(256) __nv_bfloat16 g_kh[(size_t)MM*DM];
__device__ __align__(256) __nv_bfloat16 g_kl[(size_t)MM*DM];
__device__ __align__(256) __nv_bfloat16 g_vh[(size_t)MM*DM];
__device__ __align__(256) __nv_bfloat16 g_vl[(size_t)MM*DM];
__device__ __align__(256) float g_ctx[(size_t)MM*DM];
__device__ int g_amax[8];   // 0:x 1:wq 2:wk 3:wv 4:wo 5:ctx

// ---------------------------------------------------------------------------
// PTX helpers
// ---------------------------------------------------------------------------
__device__ __forceinline__ uint32_t smem_u32(const void* p) {
    uint32_t a;
    asm("{ .reg .u64 t; cvta.to.shared.u64 t, %1; cvt.u32.u64 %0, t; }"
        : "=r"(a) : "l"(p));
    return a;
}
__device__ __forceinline__ void cpa16(uint32_t s, const void* g) {
    asm volatile("cp.async.cg.shared.global [%0], [%1], 16;" :: "r"(s), "l"(g));
}
__device__ __forceinline__ void cpa_commit() {
    asm volatile("cp.async.commit_group;" ::: "memory");
}
__device__ __forceinline__ void ldmx4(uint32_t* r, uint32_t addr) {
    asm volatile("ldmatrix.sync.aligned.m8n8.x4.shared.b16 {%0,%1,%2,%3}, [%4];"
                 : "=r"(r[0]), "=r"(r[1]), "=r"(r[2]), "=r"(r[3]) : "r"(addr));
}
__device__ __forceinline__ void mma16816(float* c, const uint32_t* a,
                                         uint32_t b0, uint32_t b1) {
    asm volatile(
        "mma.sync.aligned.m16n8k16.row.col.f32.bf16.bf16.f32 "
        "{%0,%1,%2,%3}, {%4,%5,%6,%7}, {%8,%9}, {%0,%1,%2,%3};"
        : "+f"(c[0]), "+f"(c[1]), "+f"(c[2]), "+f"(c[3])
        : "r"(a[0]), "r"(a[1]), "r"(a[2]), "r"(a[3]), "r"(b0), "r"(b1));
}
__device__ __forceinline__ void imma16832(int* c, const uint32_t* a,
                                          uint32_t b0, uint32_t b1) {
    asm volatile(
        "mma.sync.aligned.m16n8k32.row.col.s32.s8.s8.s32 "
        "{%0,%1,%2,%3}, {%4,%5,%6,%7}, {%8,%9}, {%0,%1,%2,%3};"
        : "+r"(c[0]), "+r"(c[1]), "+r"(c[2]), "+r"(c[3])
        : "r"(a[0]), "r"(a[1]), "r"(a[2]), "r"(a[3]), "r"(b0), "r"(b1));
}
__device__ __forceinline__ uint32_t packbf(float lo, float hi) {
    uint32_t r;
    asm("cvt.rn.bf16x2.f32 %0, %1, %2;" : "=r"(r) : "f"(hi), "f"(lo));
    return r;
}
__device__ __forceinline__ void q2(float x, float S, int8_t& h, int8_t& l) {
    float t = x * S;
    int i1 = __float2int_rn(t);
    int i0 = __float2int_rn((t - (float)i1) * 256.f);
    i0 = max(-127, min(127, i0));
    h = (int8_t)i1; l = (int8_t)i0;
}

// ---------------------------------------------------------------------------
// amax / quant kernels
// ---------------------------------------------------------------------------
__global__ void zero_amax_kernel(int* a) { if (threadIdx.x < 8) a[threadIdx.x] = 0; }

__global__ void absmax_kernel(const float* __restrict__ p, int n, int* __restrict__ out)
{
    float m = 0.f;
    int stride = gridDim.x * blockDim.x;
    for (int i = blockIdx.x * blockDim.x + threadIdx.x; i < n / 4; i += stride) {
        float4 v = ((const float4*)p)[i];
        m = fmaxf(m, fmaxf(fmaxf(fabsf(v.x), fabsf(v.y)),
                           fmaxf(fabsf(v.z), fabsf(v.w))));
    }
    #pragma unroll
    for (int o = 16; o; o >>= 1) m = fmaxf(m, __shfl_xor_sync(0xFFFFFFFF, m, o));
    if ((threadIdx.x & 31) == 0) atomicMax(out, __float_as_int(m));
}

__global__ void quant_kernel(const float* __restrict__ in,
                             int8_t* __restrict__ q1, int8_t* __restrict__ q0,
                             const int* __restrict__ amax, int n)
{
    int i = (blockIdx.x * blockDim.x + threadIdx.x) * 4;
    if (i >= n) return;
    float S = 127.f / __int_as_float(*amax);
    float4 v = *(const float4*)(in + i);
    char4 c1, c0;
    q2(v.x, S, (int8_t&)c1.x, (int8_t&)c0.x);
    q2(v.y, S, (int8_t&)c1.y, (int8_t&)c0.y);
    q2(v.z, S, (int8_t&)c1.z, (int8_t&)c0.z);
    q2(v.w, S, (int8_t&)c1.w, (int8_t&)c0.w);
    *(char4*)(q1 + i) = c1;
    *(char4*)(q0 + i) = c0;
}

// Transpose + quant weights: W[K,N] fp32 -> T1[N,K], T0[N,K] int8 limbs
__global__ void quant_wT_kernel(const float* __restrict__ W,
                                int8_t* __restrict__ T1, int8_t* __restrict__ T0,
                                const int* __restrict__ amax)
{
    __shared__ float t[32][33];
    float S = 127.f / __int_as_float(*amax);
    int n0 = blockIdx.x * 32, k0 = blockIdx.y * 32;
    int tx = threadIdx.x, ty = threadIdx.y; // block (32,8)
    #pragma unroll
    for (int i = 0; i < 32; i += 8)
        t[ty + i][tx] = W[(size_t)(k0 + ty + i) * DM + n0 + tx];
    __syncthreads();
    #pragma unroll
    for (int i = 0; i < 32; i += 8) {
        float v = t[tx][ty + i];   // W[k0+tx][n0+ty+i]
        int8_t h, l;
        q2(v, S, h, l);
        size_t o = (size_t)(n0 + ty + i) * DM + k0 + tx;
        T1[o] = h;
        T0[o] = l;
    }
}

// ---------------------------------------------------------------------------
// int8 2-limb GEMM: C = A[M,K] @ W^T[N,K] + bias, A = (A1 + A0/256)/S_A etc.
// terms: A1W1 (acc1) + (A1W0 + A0W1)/256 (accM); A0W0 dropped (~1e-4).
// CTA tile 128x64, 8 warps (4 M x 2 N), warp tile 32x32, k32 steps,
// double-buffered cp.async. MODE 0: fp32 [M,N]; 1: bf16 hi/lo [B,H,S,DH];
// 2: bf16 hi/lo transposed [B,H,DH,S].
// B fragment pairing: w[2j] = n-rows j*8..+7 k0-15, w[2j+1] = same n, k16-31.
// ---------------------------------------------------------------------------
#define QSTR 48
#define QA_B (128 * QSTR)     // 6144 per A limb
#define QW_B (64 * QSTR)      // 3072 per W limb
#define QSTAGE (2 * QA_B + 2 * QW_B)  // 18432
#define QSMEM (2 * QSTAGE)            // 36864

template<int MODE>
__global__ __launch_bounds__(256, 2)
void qgemm_kernel(const int8_t* __restrict__ A1, const int8_t* __restrict__ A0,
                  const int8_t* __restrict__ W1, const int8_t* __restrict__ W0,
                  const float* __restrict__ bias,
                  const int* __restrict__ sa, const int* __restrict__ sw,
                  float* __restrict__ C,
                  __nv_bfloat16* __restrict__ Oh, __nv_bfloat16* __restrict__ Ol)
{
    extern __shared__ char smem[];
    const uint32_t sbase = smem_u32(smem);
    const int tid = threadIdx.x;
    const int lane = tid & 31;
    const int wid = tid >> 5;
    const int wm = wid & 3;      // 4 x 32 rows
    const int wn = wid >> 2;     // 2 x 32 cols
    const int bm = blockIdx.y * 128;
    const int bn = blockIdx.x * 64;

    int acc1[2][4][4], accM[2][4][4];
    #pragma unroll
    for (int mi = 0; mi < 2; mi++)
        #pragma unroll
        for (int f = 0; f < 4; f++)
            #pragma unroll
            for (int e = 0; e < 4; e++) { acc1[mi][f][e] = 0; accM[mi][f][e] = 0; }

    auto load_stage = [&](int buf, int k0) {
        uint32_t sb = sbase + buf * QSTAGE;
        int r = tid >> 1, h = tid & 1;
        size_t ga = (size_t)(bm + r) * DM + k0 + h * 16;
        cpa16(sb + r * QSTR + h * 16, A1 + ga);
        cpa16(sb + QA_B + r * QSTR + h * 16, A0 + ga);
        if (tid < 128) {
            int wr = tid >> 1;
            cpa16(sb + 2 * QA_B + wr * QSTR + h * 16,
                  W1 + (size_t)(bn + wr) * DM + k0 + h * 16);
        } else {
            int wr = (tid - 128) >> 1;
            cpa16(sb + 2 * QA_B + QW_B + wr * QSTR + h * 16,
                  W0 + (size_t)(bn + wr) * DM + k0 + h * 16);
        }
    };

    const int a_row = (lane & 7) + ((lane >> 3) & 1) * 8;
    const int a_half = lane >> 4;
    const int b_row = (lane & 7) + ((lane >> 4) & 1) * 8;
    const int b_half = (lane >> 3) & 1;

    const int T = DM / 32;   // 32 k-tiles
    load_stage(0, 0);
    cpa_commit();

    for (int t = 0; t < T; t++) {
        if (t + 1 < T) {
            load_stage((t + 1) & 1, (t + 1) * 32);
            cpa_commit();
            asm volatile("cp.async.wait_group 1;" ::: "memory");
        } else {
            asm volatile("cp.async.wait_group 0;" ::: "memory");
        }
        __syncthreads();

        const uint32_t sb = sbase + (t & 1) * QSTAGE;
        uint32_t a1f[2][4], a0f[2][4];
        #pragma unroll
        for (int mi = 0; mi < 2; mi++) {
            uint32_t ra = sb + (wm * 32 + mi * 16 + a_row) * QSTR + a_half * 16;
            ldmx4(a1f[mi], ra);
            ldmx4(a0f[mi], ra + QA_B);
        }
        #pragma unroll
        for (int g = 0; g < 2; g++) {
            uint32_t w1f[4], w0f[4];
            uint32_t rb = sb + 2 * QA_B + (wn * 32 + g * 16 + b_row) * QSTR
                        + b_half * 16;
            ldmx4(w1f, rb);
            ldmx4(w0f, rb + QW_B);
            #pragma unroll
            for (int j = 0; j < 2; j++) {
                #pragma unroll
                for (int mi = 0; mi < 2; mi++) {
                    int f = g * 2 + j;
                    imma16832(acc1[mi][f], a1f[mi], w1f[2 * j], w1f[2 * j + 1]);
                    imma16832(accM[mi][f], a1f[mi], w0f[2 * j], w0f[2 * j + 1]);
                    imma16832(accM[mi][f], a0f[mi], w1f[2 * j], w1f[2 * j + 1]);
                }
            }
        }
        __syncthreads();
    }

    const float scale = (__int_as_float(*sa) * __int_as_float(*sw)) / 16129.f;

    #pragma unroll
    for (int mi = 0; mi < 2; mi++) {
        #pragma unroll
        for (int f = 0; f < 4; f++) {
            int gcol = bn + wn * 32 + f * 8 + (lane & 3) * 2;
            float b0 = __ldg(bias + gcol);
            float b1 = __ldg(bias + gcol + 1);
            #pragma unroll
            for (int half = 0; half < 2; half++) {
                int row = bm + wm * 32 + mi * 16 + (lane >> 2) + half * 8;
                float vx = ((float)acc1[mi][f][half * 2 + 0]
                          + (float)accM[mi][f][half * 2 + 0] * (1.f / 256.f)) * scale + b0;
                float vy = ((float)acc1[mi][f][half * 2 + 1]
                          + (float)accM[mi][f][half * 2 + 1] * (1.f / 256.f)) * scale + b1;
                if (MODE == 0) {
                    float2 v; v.x = vx; v.y = vy;
                    *(float2*)&C[(size_t)row * DM + gcol] = v;
                } else {
                    int hh = gcol >> 6, d = gcol & 63;
                    int b_ = row >> 11, s = row & 2047;
                    __nv_bfloat16 h0 = __float2bfloat16(vx);
                    __nv_bfloat16 h1 = __float2bfloat16(vy);
                    __nv_bfloat16 l0 = __float2bfloat16(vx - __bfloat162float(h0));
                    __nv_bfloat16 l1 = __float2bfloat16(vy - __bfloat162float(h1));
                    if (MODE == 1) {
                        size_t o = ((((size_t)b_ * HH + hh) * SS + s) * DH) + d;
                        __nv_bfloat162 ph; ph.x = h0; ph.y = h1;
                        __nv_bfloat162 pl; pl.x = l0; pl.y = l1;
                        *(__nv_bfloat162*)&Oh[o] = ph;
                        *(__nv_bfloat162*)&Ol[o] = pl;
                    } else {
                        size_t o = ((((size_t)b_ * HH + hh) * DH + d) * SS) + s;
                        Oh[o] = h0; Oh[o + SS] = h1;
                        Ol[o] = l0; Ol[o + SS] = l1;
                    }
                }
            }
        }
    }
}

// ---------------------------------------------------------------------------
// Tensor-core flash attention (3-term split bf16), 2 CTAs/SM. fp32 ctx out.
// ---------------------------------------------------------------------------
#define FSTR 72
#define FQ_B (128 * FSTR * 2)
#define FT_B (64 * FSTR * 2)
#define FO_QH 0
#define FO_QL FQ_B
#define FO_STAGE (2 * FQ_B)
#define FSK_H 0
#define FSK_L FT_B
#define FSV_H (2 * FT_B)
#define FSV_L (3 * FT_B)
#define FSTAGE_B (4 * FT_B)
#define FLASH_SMEM (FO_STAGE + 2 * FSTAGE_B)

__global__ __launch_bounds__(256, 2)
void flash_tc_kernel(const __nv_bfloat16* __restrict__ Qh,
                     const __nv_bfloat16* __restrict__ Ql,
                     const __nv_bfloat16* __restrict__ Kh,
                     const __nv_bfloat16* __restrict__ Kl,
                     const __nv_bfloat16* __restrict__ Vh,
                     const __nv_bfloat16* __restrict__ Vl,
                     float* __restrict__ ctx)
{
    extern __shared__ char smem[];
    const uint32_t sbase = smem_u32(smem);
    const int tid = threadIdx.x;
    const int lane = tid & 31;
    const int wid = tid >> 5;
    const int bh = blockIdx.y;
    const int q0 = blockIdx.x * 128;

    const size_t qbase = ((size_t)bh * SS + q0) * DH;
    const size_t kbase = (size_t)bh * SS * DH;
    const size_t vbase = (size_t)bh * DH * SS;

    #pragma unroll
    for (int i = 0; i < 4; i++) {
        int c = tid + i * 256;
        int row = c >> 3, col = c & 7;
        uint32_t so = row * 144 + col * 16;
        size_t g = qbase + (size_t)row * DH + col * 8;
        cpa16(sbase + FO_QH + so, Qh + g);
        cpa16(sbase + FO_QL + so, Ql + g);
    }
    cpa_commit();

    auto load_kv = [&](int buf, int kv0) {
        uint32_t sb = sbase + FO_STAGE + buf * FSTAGE_B;
        #pragma unroll
        for (int i = 0; i < 2; i++) {
            int c = tid + i * 256;
            int row = c >> 3, col = c & 7;
            uint32_t so = row * 144 + col * 16;
            size_t gk = kbase + (size_t)(kv0 + row) * DH + col * 8;
            size_t gv = vbase + (size_t)row * SS + kv0 + col * 8;
            cpa16(sb + FSK_H + so, Kh + gk);
            cpa16(sb + FSK_L + so, Kl + gk);
            cpa16(sb + FSV_H + so, Vh + gv);
            cpa16(sb + FSV_L + so, Vl + gv);
        }
    };

    load_kv(0, 0);
    cpa_commit();
    asm volatile("cp.async.wait_group 0;" ::: "memory");
    __syncthreads();

    const int a_row = (lane & 7) + ((lane >> 3) & 1) * 8;
    const int a_kh  = (lane >> 4) * 8;
    const int b_n   = (lane & 7) + ((lane >> 4) & 1) * 8;
    const int b_kh  = ((lane >> 3) & 1) * 8;

    float Oa[8][4];
    #pragma unroll
    for (int j = 0; j < 8; j++)
        #pragma unroll
        for (int e = 0; e < 4; e++) Oa[j][e] = 0.f;
    float m0 = -1e30f, m1 = -1e30f, l0 = 0.f, l1 = 0.f;

    const int T = SS / 64;
    for (int t = 0; t < T; t++) {
        if (t + 1 < T) {
            load_kv((t + 1) & 1, (t + 1) * 64);
            cpa_commit();
            asm volatile("cp.async.wait_group 1;" ::: "memory");
        } else {
            asm volatile("cp.async.wait_group 0;" ::: "memory");
        }
        __syncthreads();

        const uint32_t sb = sbase + FO_STAGE + (t & 1) * FSTAGE_B;

        float S[8][4];
        #pragma unroll
        for (int j = 0; j < 8; j++)
            #pragma unroll
            for (int e = 0; e < 4; e++) S[j][e] = 0.f;

        #pragma unroll
        for (int ks = 0; ks < 4; ks++) {
            uint32_t qh4[4], ql4[4];
            uint32_t ra = sbase + (wid * 16 + a_row) * 144 + (ks * 16 + a_kh) * 2;
            ldmx4(qh4, ra + FO_QH);
            ldmx4(ql4, ra + FO_QL);
            #pragma unroll
            for (int np = 0; np < 4; np++) {
                uint32_t kh4[4], kl4[4];
                uint32_t rb = sb + (np * 16 + b_n) * 144 + (ks * 16 + b_kh) * 2;
                ldmx4(kh4, rb + FSK_H);
                ldmx4(kl4, rb + FSK_L);
                mma16816(S[np * 2 + 0], qh4, kh4[0], kh4[1]);
                mma16816(S[np * 2 + 1], qh4, kh4[2], kh4[3]);
                mma16816(S[np * 2 + 0], qh4, kl4[0], kl4[1]);
                mma16816(S[np * 2 + 1], qh4, kl4[2], kl4[3]);
                mma16816(S[np * 2 + 0], ql4, kh4[0], kh4[1]);
                mma16816(S[np * 2 + 1], ql4, kh4[2], kh4[3]);
            }
        }

        float rx0 = -1e30f, rx1 = -1e30f;
        #pragma unroll
        for (int j = 0; j < 8; j++) {
            #pragma unroll
            for (int e = 0; e < 4; e++) S[j][e] *= 0.125f;
            rx0 = fmaxf(rx0, fmaxf(S[j][0], S[j][1]));
            rx1 = fmaxf(rx1, fmaxf(S[j][2], S[j][3]));
        }
        rx0 = fmaxf(rx0, __shfl_xor_sync(0xFFFFFFFF, rx0, 1));
        rx0 = fmaxf(rx0, __shfl_xor_sync(0xFFFFFFFF, rx0, 2));
        rx1 = fmaxf(rx1, __shfl_xor_sync(0xFFFFFFFF, rx1, 1));
        rx1 = fmaxf(rx1, __shfl_xor_sync(0xFFFFFFFF, rx1, 2));
        float mn0 = fmaxf(m0, rx0), mn1 = fmaxf(m1, rx1);
        float al0 = __expf(m0 - mn0), al1 = __expf(m1 - mn1);
        l0 *= al0; l1 *= al1;
        #pragma unroll
        for (int j = 0; j < 8; j++) {
            Oa[j][0] *= al0; Oa[j][1] *= al0;
            Oa[j][2] *= al1; Oa[j][3] *= al1;
        }
        #pragma unroll
        for (int j = 0; j < 8; j++) {
            S[j][0] = __expf(S[j][0] - mn0);
            S[j][1] = __expf(S[j][1] - mn0);
            S[j][2] = __expf(S[j][2] - mn1);
            S[j][3] = __expf(S[j][3] - mn1);
            l0 += S[j][0] + S[j][1];
            l1 += S[j][2] + S[j][3];
        }
        m0 = mn0; m1 = mn1;

        #pragma unroll
        for (int kc = 0; kc < 4; kc++) {
            uint32_t pah[4], pal[4];
            #pragma unroll
            for (int u = 0; u < 2; u++) {
                const float* sp = S[kc * 2 + u];
                uint32_t h01 = packbf(sp[0], sp[1]);
                uint32_t h23 = packbf(sp[2], sp[3]);
                float hl0 = __uint_as_float(h01 << 16);
                float hh0 = __uint_as_float(h01 & 0xFFFF0000u);
                float hl1 = __uint_as_float(h23 << 16);
                float hh1 = __uint_as_float(h23 & 0xFFFF0000u);
                pah[u * 2 + 0] = h01;
                pah[u * 2 + 1] = h23;
                pal[u * 2 + 0] = packbf(sp[0] - hl0, sp[1] - hh0);
                pal[u * 2 + 1] = packbf(sp[2] - hl1, sp[3] - hh1);
            }
            #pragma unroll
            for (int np = 0; np < 4; np++) {
                uint32_t vh4[4], vl4[4];
                uint32_t rb = sb + (np * 16 + b_n) * 144 + (kc * 16 + b_kh) * 2;
                ldmx4(vh4, rb + FSV_H);
                ldmx4(vl4, rb + FSV_L);
                mma16816(Oa[np * 2 + 0], pah, vh4[0], vh4[1]);
                mma16816(Oa[np * 2 + 1], pah, vh4[2], vh4[3]);
                mma16816(Oa[np * 2 + 0], pah, vl4[0], vl4[1]);
                mma16816(Oa[np * 2 + 1], pah, vl4[2], vl4[3]);
                mma16816(Oa[np * 2 + 0], pal, vh4[0], vh4[1]);
                mma16816(Oa[np * 2 + 1], pal, vh4[2], vh4[3]);
            }
        }
        __syncthreads();
    }

    l0 += __shfl_xor_sync(0xFFFFFFFF, l0, 1);
    l0 += __shfl_xor_sync(0xFFFFFFFF, l0, 2);
    l1 += __shfl_xor_sync(0xFFFFFFFF, l1, 1);
    l1 += __shfl_xor_sync(0xFFFFFFFF, l1, 2);
    float inv0 = 1.f / l0, inv1 = 1.f / l1;

    const int b_ = bh >> 4, h = bh & 15;
    const int r0 = q0 + wid * 16 + (lane >> 2);
    const int col = h * 64 + (lane & 3) * 2;
    #pragma unroll
    for (int nf = 0; nf < 8; nf++) {
        float2 v0, v1;
        v0.x = Oa[nf][0] * inv0; v0.y = Oa[nf][1] * inv0;
        v1.x = Oa[nf][2] * inv1; v1.y = Oa[nf][3] * inv1;
        *(float2*)&ctx[((size_t)b_ * SS + r0) * DM + col + nf * 8] = v0;
        *(float2*)&ctx[((size_t)b_ * SS + r0 + 8) * DM + col + nf * 8] = v1;
    }
}

// ---------------------------------------------------------------------------
extern "C" void kernel_launch(void* const* d_in, const int* in_sizes, int n_in,
                              void* d_out, int out_size)
{
    const float* x  = (const float*)d_in[0];
    const float* wq = (const float*)d_in[1];
    const float* bq = (const float*)d_in[2];
    const float* wk = (const float*)d_in[3];
    const float* bk = (const float*)d_in[4];
    const float* wv = (const float*)d_in[5];
    const float* bv = (const float*)d_in[6];
    const float* wo = (const float*)d_in[7];
    const float* bo = (const float*)d_in[8];
    float* out = (float*)d_out;

    int8_t *xq1, *xq0, *wq1, *wq0, *wk1, *wk0, *wv1, *wv0, *wo1, *wo0, *cq1, *cq0;
    __nv_bfloat16 *qh, *ql, *kh, *kl, *vh, *vl;
    float* cp;
    int* am;
    cudaGetSymbolAddress((void**)&xq1, g_xq1);
    cudaGetSymbolAddress((void**)&xq0, g_xq0);
    cudaGetSymbolAddress((void**)&wq1, g_wq1);
    cudaGetSymbolAddress((void**)&wq0, g_wq0);
    cudaGetSymbolAddress((void**)&wk1, g_wk1);
    cudaGetSymbolAddress((void**)&wk0, g_wk0);
    cudaGetSymbolAddress((void**)&wv1, g_wv1);
    cudaGetSymbolAddress((void**)&wv0, g_wv0);
    cudaGetSymbolAddress((void**)&wo1, g_wo1);
    cudaGetSymbolAddress((void**)&wo0, g_wo0);
    cudaGetSymbolAddress((void**)&cq1, g_cq1);
    cudaGetSymbolAddress((void**)&cq0, g_cq0);
    cudaGetSymbolAddress((void**)&qh, g_qh);
    cudaGetSymbolAddress((void**)&ql, g_ql);
    cudaGetSymbolAddress((void**)&kh, g_kh);
    cudaGetSymbolAddress((void**)&kl, g_kl);
    cudaGetSymbolAddress((void**)&vh, g_vh);
    cudaGetSymbolAddress((void**)&vl, g_vl);
    cudaGetSymbolAddress((void**)&cp, g_ctx);
    cudaGetSymbolAddress((void**)&am, g_amax);

    cudaFuncSetAttribute(flash_tc_kernel,
                         cudaFuncAttributeMaxDynamicSharedMemorySize, FLASH_SMEM);

    const int NX = MM * DM;   // 4M
    const int NW = DM * DM;   // 1M

    // scales
    zero_amax_kernel<<<1, 32>>>(am);
    absmax_kernel<<<512, 256>>>(x, NX, am + 0);
    absmax_kernel<<<128, 256>>>(wq, NW, am + 1);
    absmax_kernel<<<128, 256>>>(wk, NW, am + 2);
    absmax_kernel<<<128, 256>>>(wv, NW, am + 3);
    absmax_kernel<<<128, 256>>>(wo, NW, am + 4);

    // quantize
    quant_kernel<<<NX / 1024, 256>>>(x, xq1, xq0, am + 0, NX);
    dim3 wg(DM / 32, DM / 32), wb(32, 8);
    quant_wT_kernel<<<wg, wb>>>(wq, wq1, wq0, am + 1);
    quant_wT_kernel<<<wg, wb>>>(wk, wk1, wk0, am + 2);
    quant_wT_kernel<<<wg, wb>>>(wv, wv1, wv0, am + 3);
    quant_wT_kernel<<<wg, wb>>>(wo, wo1, wo0, am + 4);

    // QKV projections (int8 tensor cores) -> split bf16 head layouts
    dim3 qg(DM / 64, MM / 128);  // (16, 32)
    qgemm_kernel<1><<<qg, 256, QSMEM>>>(xq1, xq0, wq1, wq0, bq, am + 0, am + 1,
                                        nullptr, qh, ql);
    qgemm_kernel<1><<<qg, 256, QSMEM>>>(xq1, xq0, wk1, wk0, bk, am + 0, am + 2,
                                        nullptr, kh, kl);
    qgemm_kernel<2><<<qg, 256, QSMEM>>>(xq1, xq0, wv1, wv0, bv, am + 0, am + 3,
                                        nullptr, vh, vl);

    // attention (bf16 tensor cores) -> fp32 ctx
    flash_tc_kernel<<<dim3(SS / 128, BB * HH), 256, FLASH_SMEM>>>(
        qh, ql, kh, kl, vh, vl, cp);

    // output projection (int8)
    absmax_kernel<<<512, 256>>>(cp, NX, am + 5);
    quant_kernel<<<NX / 1024, 256>>>(cp, cq1, cq0, am + 5, NX);
    qgemm_kernel<0><<<qg, 256, QSMEM>>>(cq1, cq0, wo1, wo0, bo, am + 5, am + 4,
                                        out, nullptr, nullptr);
}

// round 9
// speedup vs baseline: 2.2465x; 2.2465x over previous
#include <cuda_runtime.h>
#include <cuda_bf16.h>
#include <cuda_fp16.h>
#include <math.h>
#include <stdint.h>

#define BB 2
#define HH 16
#define SS 2048
#define DH 64
#define DM 1024
#define MM (BB*SS)   // 4096

// ---------------------------------------------------------------------------
// Scratch (device globals)
// ---------------------------------------------------------------------------
__device__ __align__(256) __nv_bfloat16 g_xh[(size_t)MM*DM];
__device__ __align__(256) __nv_bfloat16 g_xl[(size_t)MM*DM];
__device__ __align__(256) __nv_bfloat16 g_wqh[(size_t)DM*DM];
__device__ __align__(256) __nv_bfloat16 g_wql[(size_t)DM*DM];
__device__ __align__(256) __nv_bfloat16 g_wkh[(size_t)DM*DM];
__device__ __align__(256) __nv_bfloat16 g_wkl[(size_t)DM*DM];
__device__ __align__(256) __nv_bfloat16 g_wvh[(size_t)DM*DM];
__device__ __align__(256) __nv_bfloat16 g_wvl[(size_t)DM*DM];
__device__ __align__(256) __nv_bfloat16 g_woh[(size_t)DM*DM];
__device__ __align__(256) __nv_bfloat16 g_wol[(size_t)DM*DM];
// Q,K fp16 [B,H,S,DH]; V fp16 transposed [B,H,DH,S]
__device__ __align__(256) __half g_qf[(size_t)MM*DM];
__device__ __align__(256) __half g_kf[(size_t)MM*DM];
__device__ __align__(256) __half g_vf[(size_t)MM*DM];
// ctx split bf16 (written directly by flash epilogue)
__device__ __align__(256) __nv_bfloat16 g_ch[(size_t)MM*DM];
__device__ __align__(256) __nv_bfloat16 g_cl[(size_t)MM*DM];

// ---------------------------------------------------------------------------
// PTX helpers
// ---------------------------------------------------------------------------
__device__ __forceinline__ uint32_t smem_u32(const void* p) {
    uint32_t a;
    asm("{ .reg .u64 t; cvta.to.shared.u64 t, %1; cvt.u32.u64 %0, t; }"
        : "=r"(a) : "l"(p));
    return a;
}
__device__ __forceinline__ void cpa16(uint32_t s, const void* g) {
    asm volatile("cp.async.cg.shared.global [%0], [%1], 16;" :: "r"(s), "l"(g));
}
__device__ __forceinline__ void cpa_commit() {
    asm volatile("cp.async.commit_group;" ::: "memory");
}
__device__ __forceinline__ void ldmx4(uint32_t* r, uint32_t addr) {
    asm volatile("ldmatrix.sync.aligned.m8n8.x4.shared.b16 {%0,%1,%2,%3}, [%4];"
                 : "=r"(r[0]), "=r"(r[1]), "=r"(r[2]), "=r"(r[3]) : "r"(addr));
}
__device__ __forceinline__ void mma16816(float* c, const uint32_t* a,
                                         uint32_t b0, uint32_t b1) {
    asm volatile(
        "mma.sync.aligned.m16n8k16.row.col.f32.bf16.bf16.f32 "
        "{%0,%1,%2,%3}, {%4,%5,%6,%7}, {%8,%9}, {%0,%1,%2,%3};"
        : "+f"(c[0]), "+f"(c[1]), "+f"(c[2]), "+f"(c[3])
        : "r"(a[0]), "r"(a[1]), "r"(a[2]), "r"(a[3]), "r"(b0), "r"(b1));
}
__device__ __forceinline__ void mmaf16(float* c, const uint32_t* a,
                                       uint32_t b0, uint32_t b1) {
    asm volatile(
        "mma.sync.aligned.m16n8k16.row.col.f32.f16.f16.f32 "
        "{%0,%1,%2,%3}, {%4,%5,%6,%7}, {%8,%9}, {%0,%1,%2,%3};"
        : "+f"(c[0]), "+f"(c[1]), "+f"(c[2]), "+f"(c[3])
        : "r"(a[0]), "r"(a[1]), "r"(a[2]), "r"(a[3]), "r"(b0), "r"(b1));
}
__device__ __forceinline__ uint32_t packh(float lo, float hi) {
    __half2 h = __floats2half2_rn(lo, hi);
    return *reinterpret_cast<uint32_t*>(&h);
}

// ---------------------------------------------------------------------------
// Split fp32 -> bf16 hi + bf16 lo (elementwise, x)
// ---------------------------------------------------------------------------
__global__ void split_kernel(const float* __restrict__ in,
                             __nv_bfloat16* __restrict__ hi,
                             __nv_bfloat16* __restrict__ lo, int n)
{
    int i = (blockIdx.x * blockDim.x + threadIdx.x) * 4;
    if (i >= n) return;
    float4 v = *(const float4*)(in + i);
    __nv_bfloat16 h0 = __float2bfloat16(v.x);
    __nv_bfloat16 h1 = __float2bfloat16(v.y);
    __nv_bfloat16 h2 = __float2bfloat16(v.z);
    __nv_bfloat16 h3 = __float2bfloat16(v.w);
    __nv_bfloat16 l0 = __float2bfloat16(v.x - __bfloat162float(h0));
    __nv_bfloat16 l1 = __float2bfloat16(v.y - __bfloat162float(h1));
    __nv_bfloat16 l2 = __float2bfloat16(v.z - __bfloat162float(h2));
    __nv_bfloat16 l3 = __float2bfloat16(v.w - __bfloat162float(h3));
    __nv_bfloat162 ph0; ph0.x = h0; ph0.y = h1;
    __nv_bfloat162 ph1; ph1.x = h2; ph1.y = h3;
    __nv_bfloat162 pl0; pl0.x = l0; pl0.y = l1;
    __nv_bfloat162 pl1; pl1.x = l2; pl1.y = l3;
    ((__nv_bfloat162*)(hi + i))[0] = ph0;
    ((__nv_bfloat162*)(hi + i))[1] = ph1;
    ((__nv_bfloat162*)(lo + i))[0] = pl0;
    ((__nv_bfloat162*)(lo + i))[1] = pl1;
}

// ---------------------------------------------------------------------------
// Transpose + split weights: W[K,N] fp32 -> Th[N,K], Tl[N,K] bf16
// ---------------------------------------------------------------------------
__global__ void wsplit_kernel(const float* __restrict__ W,
                              __nv_bfloat16* __restrict__ Th,
                              __nv_bfloat16* __restrict__ Tl)
{
    __shared__ float t[32][33];
    int n0 = blockIdx.x * 32, k0 = blockIdx.y * 32;
    int tx = threadIdx.x, ty = threadIdx.y; // block (32, 8)
    #pragma unroll
    for (int i = 0; i < 32; i += 8)
        t[ty + i][tx] = W[(size_t)(k0 + ty + i) * DM + n0 + tx];
    __syncthreads();
    #pragma unroll
    for (int i = 0; i < 32; i += 8) {
        float v = t[tx][ty + i];   // = W[k0+tx][n0+ty+i]
        __nv_bfloat16 h = __float2bfloat16(v);
        __nv_bfloat16 l = __float2bfloat16(v - __bfloat162float(h));
        size_t o = (size_t)(n0 + ty + i) * DM + k0 + tx;
        Th[o] = h;
        Tl[o] = l;
    }
}

// ---------------------------------------------------------------------------
// mma.sync bf16 split-GEMM: C = (Ah+Al)[M,K] @ (Wh+Wl)^T[N,K] + bias
// MODE 0: fp32 out [M,N].  MODE 1: fp16 out in [B,H,S,DH].
// MODE 2: fp16 out transposed [B,H,DH,S].
// ---------------------------------------------------------------------------
#define GBM 128
#define GBN 128
#define GBK 32
#define TILE_B (GBM * 40 * 2)  // 80B padded rows, 10240 B per matrix tile
#define STAGE_B (4 * TILE_B)
#define GEMM_SMEM (2 * STAGE_B)
#define O_AH 0
#define O_AL TILE_B
#define O_WH (2 * TILE_B)
#define O_WL (3 * TILE_B)

template<int MODE>
__global__ __launch_bounds__(256, 2)
void gemm_bf16_kernel(const __nv_bfloat16* __restrict__ Ah,
                      const __nv_bfloat16* __restrict__ Al,
                      const __nv_bfloat16* __restrict__ Wh,
                      const __nv_bfloat16* __restrict__ Wl,
                      const float* __restrict__ bias,
                      float* __restrict__ C,
                      __half* __restrict__ Of)
{
    extern __shared__ char smem[];
    const uint32_t sbase = smem_u32(smem);
    const int tid = threadIdx.x;
    const int lane = tid & 31;
    const int wid = tid >> 5;
    const int wm = wid & 3;
    const int wn = wid >> 2;
    const int bm = blockIdx.y * GBM;
    const int bn = blockIdx.x * GBN;

    float acc[2][8][4];
    #pragma unroll
    for (int i = 0; i < 2; i++)
        #pragma unroll
        for (int j = 0; j < 8; j++)
            #pragma unroll
            for (int e = 0; e < 4; e++) acc[i][j][e] = 0.f;

    const int lrow = tid >> 1;
    const int lcol = (tid & 1) * 2;

    auto load_stage = [&](int buf, int k0) {
        uint32_t sb = sbase + buf * STAGE_B;
        uint32_t so0 = lrow * 80 + lcol * 16;
        uint32_t so1 = so0 + 16;
        size_t ga = (size_t)(bm + lrow) * DM + k0 + lcol * 8;
        size_t gw = (size_t)(bn + lrow) * DM + k0 + lcol * 8;
        cpa16(sb + O_AH + so0, Ah + ga);
        cpa16(sb + O_AH + so1, Ah + ga + 8);
        cpa16(sb + O_AL + so0, Al + ga);
        cpa16(sb + O_AL + so1, Al + ga + 8);
        cpa16(sb + O_WH + so0, Wh + gw);
        cpa16(sb + O_WH + so1, Wh + gw + 8);
        cpa16(sb + O_WL + so0, Wl + gw);
        cpa16(sb + O_WL + so1, Wl + gw + 8);
    };

    const int a_row = (lane & 7) + ((lane >> 3) & 1) * 8;
    const int a_kh  = (lane >> 4) * 8;
    const int b_n   = (lane & 7) + ((lane >> 4) & 1) * 8;
    const int b_kh  = ((lane >> 3) & 1) * 8;

    const int T = DM / GBK;
    load_stage(0, 0);
    cpa_commit();

    for (int t = 0; t < T; t++) {
        if (t + 1 < T) {
            load_stage((t + 1) & 1, (t + 1) * GBK);
            cpa_commit();
            asm volatile("cp.async.wait_group 1;" ::: "memory");
        } else {
            asm volatile("cp.async.wait_group 0;" ::: "memory");
        }
        __syncthreads();

        const uint32_t sb = sbase + (t & 1) * STAGE_B;
        #pragma unroll
        for (int ks = 0; ks < 2; ks++) {
            uint32_t ah[2][4], al[2][4];
            #pragma unroll
            for (int mi = 0; mi < 2; mi++) {
                uint32_t ra = sb + (wm * 32 + mi * 16 + a_row) * 80
                            + (ks * 16 + a_kh) * 2;
                ldmx4(ah[mi], ra + O_AH);
                ldmx4(al[mi], ra + O_AL);
            }
            #pragma unroll
            for (int np = 0; np < 4; np++) {
                uint32_t bh[4], bl[4];
                uint32_t rb = sb + (wn * 64 + np * 16 + b_n) * 80
                            + (ks * 16 + b_kh) * 2;
                ldmx4(bh, rb + O_WH);
                ldmx4(bl, rb + O_WL);
                #pragma unroll
                for (int mi = 0; mi < 2; mi++) {
                    mma16816(acc[mi][np * 2 + 0], ah[mi], bh[0], bh[1]);
                    mma16816(acc[mi][np * 2 + 1], ah[mi], bh[2], bh[3]);
                    mma16816(acc[mi][np * 2 + 0], al[mi], bh[0], bh[1]);
                    mma16816(acc[mi][np * 2 + 1], al[mi], bh[2], bh[3]);
                    mma16816(acc[mi][np * 2 + 0], ah[mi], bl[0], bl[1]);
                    mma16816(acc[mi][np * 2 + 1], ah[mi], bl[2], bl[3]);
                }
            }
        }
        __syncthreads();
    }

    // Epilogue
    #pragma unroll
    for (int mi = 0; mi < 2; mi++) {
        #pragma unroll
        for (int nf = 0; nf < 8; nf++) {
            int gcol = bn + wn * 64 + nf * 8 + (lane & 3) * 2;
            float b0 = __ldg(bias + gcol);
            float b1 = __ldg(bias + gcol + 1);
            #pragma unroll
            for (int half = 0; half < 2; half++) {
                int row = bm + wm * 32 + mi * 16 + (lane >> 2) + half * 8;
                float vx = acc[mi][nf][half * 2 + 0] + b0;
                float vy = acc[mi][nf][half * 2 + 1] + b1;
                if (MODE == 0) {
                    float2 v; v.x = vx; v.y = vy;
                    *(float2*)&C[(size_t)row * DM + gcol] = v;
                } else {
                    int hh = gcol >> 6, d = gcol & 63;
                    int b_ = row >> 11, s = row & 2047;
                    if (MODE == 1) {
                        size_t o = ((((size_t)b_ * HH + hh) * SS + s) * DH) + d;
                        __half2 hv = __floats2half2_rn(vx, vy);
                        *(__half2*)&Of[o] = hv;
                    } else {
                        size_t o = ((((size_t)b_ * HH + hh) * DH + d) * SS) + s;
                        Of[o] = __float2half_rn(vx);
                        Of[o + SS] = __float2half_rn(vy);
                    }
                }
            }
        }
    }
}

// ---------------------------------------------------------------------------
// Tensor-core flash attention, single-term fp16 QK and PV, fp32 softmax.
// 256 threads (8 warps x 16 q-rows), 64-key double-buffered chunks, 2 CTAs/SM.
// Epilogue writes ctx as bf16 hi/lo (row-major [MM, DM]).
// ---------------------------------------------------------------------------
#define FQSZ (128 * 144)           // 18432: Q tile, 144B padded rows
#define FKOFF 0
#define FVOFF (64 * 144)           // 9216
#define FSTAGE (2 * 64 * 144)      // 18432 per stage (K + V)
#define FLASH_SMEM (FQSZ + 2 * FSTAGE)  // 55296

__global__ __launch_bounds__(256, 2)
void flash_fp16_kernel(const __half* __restrict__ Qf,
                       const __half* __restrict__ Kf,
                       const __half* __restrict__ Vf,
                       __nv_bfloat16* __restrict__ Ch,
                       __nv_bfloat16* __restrict__ Cl)
{
    extern __shared__ char smem[];
    const uint32_t sbase = smem_u32(smem);
    const int tid = threadIdx.x;
    const int lane = tid & 31;
    const int wid = tid >> 5;              // 0..7
    const int bh = blockIdx.y;             // b*HH + h
    const int q0 = blockIdx.x * 128;

    const size_t qbase = ((size_t)bh * SS + q0) * DH;
    const size_t kbase = (size_t)bh * SS * DH;
    const size_t vbase = (size_t)bh * DH * SS;

    // ---- load Q tile (128 x 64 fp16): 1024 16B chunks ----
    #pragma unroll
    for (int i = 0; i < 4; i++) {
        int c = tid + i * 256;
        int row = c >> 3, col = c & 7;
        cpa16(sbase + row * 144 + col * 16, Qf + qbase + (size_t)row * DH + col * 8);
    }
    cpa_commit();

    auto load_kv = [&](int buf, int kv0) {
        uint32_t sb = sbase + FQSZ + buf * FSTAGE;
        #pragma unroll
        for (int i = 0; i < 2; i++) {
            int c = tid + i * 256;         // 512 chunks per matrix
            int row = c >> 3, col = c & 7;
            uint32_t so = row * 144 + col * 16;
            cpa16(sb + FKOFF + so, Kf + kbase + (size_t)(kv0 + row) * DH + col * 8);
            cpa16(sb + FVOFF + so, Vf + vbase + (size_t)row * SS + kv0 + col * 8);
        }
    };

    load_kv(0, 0);
    cpa_commit();
    asm volatile("cp.async.wait_group 0;" ::: "memory");
    __syncthreads();

    const int a_row = (lane & 7) + ((lane >> 3) & 1) * 8;
    const int a_kh  = (lane >> 4) * 8;
    const int b_n   = (lane & 7) + ((lane >> 4) & 1) * 8;
    const int b_kh  = ((lane >> 3) & 1) * 8;

    float Oa[8][4];
    #pragma unroll
    for (int j = 0; j < 8; j++)
        #pragma unroll
        for (int e = 0; e < 4; e++) Oa[j][e] = 0.f;
    float m0 = -1e30f, m1 = -1e30f, l0 = 0.f, l1 = 0.f;

    const int T = SS / 64;  // 32
    for (int t = 0; t < T; t++) {
        if (t + 1 < T) {
            load_kv((t + 1) & 1, (t + 1) * 64);
            cpa_commit();
            asm volatile("cp.async.wait_group 1;" ::: "memory");
        } else {
            asm volatile("cp.async.wait_group 0;" ::: "memory");
        }
        __syncthreads();

        const uint32_t sb = sbase + FQSZ + (t & 1) * FSTAGE;

        // ---- S = Q K^T (single fp16 term) ----
        float S[8][4];
        #pragma unroll
        for (int j = 0; j < 8; j++)
            #pragma unroll
            for (int e = 0; e < 4; e++) S[j][e] = 0.f;

        #pragma unroll
        for (int ks = 0; ks < 4; ks++) {
            uint32_t qf4[4];
            ldmx4(qf4, sbase + (wid * 16 + a_row) * 144 + (ks * 16 + a_kh) * 2);
            #pragma unroll
            for (int np = 0; np < 4; np++) {
                uint32_t kf4[4];
                ldmx4(kf4, sb + FKOFF + (np * 16 + b_n) * 144 + (ks * 16 + b_kh) * 2);
                mmaf16(S[np * 2 + 0], qf4, kf4[0], kf4[1]);
                mmaf16(S[np * 2 + 1], qf4, kf4[2], kf4[3]);
            }
        }

        // ---- online softmax ----
        float rx0 = -1e30f, rx1 = -1e30f;
        #pragma unroll
        for (int j = 0; j < 8; j++) {
            #pragma unroll
            for (int e = 0; e < 4; e++) S[j][e] *= 0.125f;
            rx0 = fmaxf(rx0, fmaxf(S[j][0], S[j][1]));
            rx1 = fmaxf(rx1, fmaxf(S[j][2], S[j][3]));
        }
        rx0 = fmaxf(rx0, __shfl_xor_sync(0xFFFFFFFF, rx0, 1));
        rx0 = fmaxf(rx0, __shfl_xor_sync(0xFFFFFFFF, rx0, 2));
        rx1 = fmaxf(rx1, __shfl_xor_sync(0xFFFFFFFF, rx1, 1));
        rx1 = fmaxf(rx1, __shfl_xor_sync(0xFFFFFFFF, rx1, 2));
        float mn0 = fmaxf(m0, rx0), mn1 = fmaxf(m1, rx1);
        float al0 = __expf(m0 - mn0), al1 = __expf(m1 - mn1);
        l0 *= al0; l1 *= al1;
        #pragma unroll
        for (int j = 0; j < 8; j++) {
            Oa[j][0] *= al0; Oa[j][1] *= al0;
            Oa[j][2] *= al1; Oa[j][3] *= al1;
        }
        #pragma unroll
        for (int j = 0; j < 8; j++) {
            S[j][0] = __expf(S[j][0] - mn0);
            S[j][1] = __expf(S[j][1] - mn0);
            S[j][2] = __expf(S[j][2] - mn1);
            S[j][3] = __expf(S[j][3] - mn1);
            l0 += S[j][0] + S[j][1];
            l1 += S[j][2] + S[j][3];
        }
        m0 = mn0; m1 = mn1;

        // ---- O += P V (single fp16 term) ----
        #pragma unroll
        for (int kc = 0; kc < 4; kc++) {
            uint32_t pa[4];
            #pragma unroll
            for (int u = 0; u < 2; u++) {
                const float* sp = S[kc * 2 + u];
                pa[u * 2 + 0] = packh(sp[0], sp[1]);
                pa[u * 2 + 1] = packh(sp[2], sp[3]);
            }
            #pragma unroll
            for (int np = 0; np < 4; np++) {
                uint32_t vf4[4];
                ldmx4(vf4, sb + FVOFF + (np * 16 + b_n) * 144 + (kc * 16 + b_kh) * 2);
                mmaf16(Oa[np * 2 + 0], pa, vf4[0], vf4[1]);
                mmaf16(Oa[np * 2 + 1], pa, vf4[2], vf4[3]);
            }
        }
        __syncthreads();
    }

    // ---- finalize: write ctx as bf16 hi/lo, row-major [MM, DM] ----
    l0 += __shfl_xor_sync(0xFFFFFFFF, l0, 1);
    l0 += __shfl_xor_sync(0xFFFFFFFF, l0, 2);
    l1 += __shfl_xor_sync(0xFFFFFFFF, l1, 1);
    l1 += __shfl_xor_sync(0xFFFFFFFF, l1, 2);
    float inv0 = 1.f / l0, inv1 = 1.f / l1;

    const int b_ = bh >> 4, h = bh & 15;
    const int r0 = q0 + wid * 16 + (lane >> 2);
    const int col = h * 64 + (lane & 3) * 2;
    #pragma unroll
    for (int nf = 0; nf < 8; nf++) {
        #pragma unroll
        for (int half = 0; half < 2; half++) {
            float inv = half ? inv1 : inv0;
            float vx = Oa[nf][half * 2 + 0] * inv;
            float vy = Oa[nf][half * 2 + 1] * inv;
            __nv_bfloat16 h0 = __float2bfloat16(vx);
            __nv_bfloat16 h1 = __float2bfloat16(vy);
            __nv_bfloat16 lo0 = __float2bfloat16(vx - __bfloat162float(h0));
            __nv_bfloat16 lo1 = __float2bfloat16(vy - __bfloat162float(h1));
            size_t o = ((size_t)b_ * SS + r0 + half * 8) * DM + col + nf * 8;
            __nv_bfloat162 ph; ph.x = h0; ph.y = h1;
            __nv_bfloat162 pl; pl.x = lo0; pl.y = lo1;
            *(__nv_bfloat162*)&Ch[o] = ph;
            *(__nv_bfloat162*)&Cl[o] = pl;
        }
    }
}

// ---------------------------------------------------------------------------
extern "C" void kernel_launch(void* const* d_in, const int* in_sizes, int n_in,
                              void* d_out, int out_size)
{
    const float* x  = (const float*)d_in[0];
    const float* wq = (const float*)d_in[1];
    const float* bq = (const float*)d_in[2];
    const float* wk = (const float*)d_in[3];
    const float* bk = (const float*)d_in[4];
    const float* wv = (const float*)d_in[5];
    const float* bv = (const float*)d_in[6];
    const float* wo = (const float*)d_in[7];
    const float* bo = (const float*)d_in[8];
    float* out = (float*)d_out;

    __nv_bfloat16 *xh, *xl, *wqh, *wql, *wkh, *wkl, *wvh, *wvl, *woh, *wol, *ch, *cl;
    __half *qf, *kf, *vf;
    cudaGetSymbolAddress((void**)&xh, g_xh);
    cudaGetSymbolAddress((void**)&xl, g_xl);
    cudaGetSymbolAddress((void**)&wqh, g_wqh);
    cudaGetSymbolAddress((void**)&wql, g_wql);
    cudaGetSymbolAddress((void**)&wkh, g_wkh);
    cudaGetSymbolAddress((void**)&wkl, g_wkl);
    cudaGetSymbolAddress((void**)&wvh, g_wvh);
    cudaGetSymbolAddress((void**)&wvl, g_wvl);
    cudaGetSymbolAddress((void**)&woh, g_woh);
    cudaGetSymbolAddress((void**)&wol, g_wol);
    cudaGetSymbolAddress((void**)&qf, g_qf);
    cudaGetSymbolAddress((void**)&kf, g_kf);
    cudaGetSymbolAddress((void**)&vf, g_vf);
    cudaGetSymbolAddress((void**)&ch, g_ch);
    cudaGetSymbolAddress((void**)&cl, g_cl);

    cudaFuncSetAttribute(gemm_bf16_kernel<0>,
                         cudaFuncAttributeMaxDynamicSharedMemorySize, GEMM_SMEM);
    cudaFuncSetAttribute(gemm_bf16_kernel<1>,
                         cudaFuncAttributeMaxDynamicSharedMemorySize, GEMM_SMEM);
    cudaFuncSetAttribute(gemm_bf16_kernel<2>,
                         cudaFuncAttributeMaxDynamicSharedMemorySize, GEMM_SMEM);
    cudaFuncSetAttribute(flash_fp16_kernel,
                         cudaFuncAttributeMaxDynamicSharedMemorySize, FLASH_SMEM);

    // Split inputs
    const int NX = MM * DM;
    split_kernel<<<NX / (256 * 4), 256>>>(x, xh, xl, NX);
    dim3 wg(DM / 32, DM / 32), wb(32, 8);
    wsplit_kernel<<<wg, wb>>>(wq, wqh, wql);
    wsplit_kernel<<<wg, wb>>>(wk, wkh, wkl);
    wsplit_kernel<<<wg, wb>>>(wv, wvh, wvl);
    wsplit_kernel<<<wg, wb>>>(wo, woh, wol);

    // QKV projections (bf16 3-term) -> fp16 head layouts
    dim3 gg(DM / GBN, MM / GBM);  // (8, 32)
    gemm_bf16_kernel<1><<<gg, 256, GEMM_SMEM>>>(xh, xl, wqh, wql, bq, nullptr, qf);
    gemm_bf16_kernel<1><<<gg, 256, GEMM_SMEM>>>(xh, xl, wkh, wkl, bk, nullptr, kf);
    gemm_bf16_kernel<2><<<gg, 256, GEMM_SMEM>>>(xh, xl, wvh, wvl, bv, nullptr, vf);

    // Tensor-core attention (fp16 single-term), writes ctx split bf16
    flash_fp16_kernel<<<dim3(SS / 128, BB * HH), 256, FLASH_SMEM>>>(
        qf, kf, vf, ch, cl);

    // Output projection (bf16 3-term, exact)
    gemm_bf16_kernel<0><<<gg, 256, GEMM_SMEM>>>(ch, cl, woh, wol, bo, out, nullptr);
}

// round 10
// speedup vs baseline: 2.8419x; 1.2650x over previous
#include <cuda_runtime.h>
#include <cuda_bf16.h>
#include <cuda_fp16.h>
#include <math.h>
#include <stdint.h>

#define BB 2
#define HH 16
#define SS 2048
#define DH 64
#define DM 1024
#define MM (BB*SS)   // 4096

// ---------------------------------------------------------------------------
// Scratch (device globals)
// ---------------------------------------------------------------------------
// x as fp16 2-limb (near-exact), weights single fp16 (transposed [N,K])
__device__ __align__(256) __half g_xh[(size_t)MM*DM];
__device__ __align__(256) __half g_xl[(size_t)MM*DM];
__device__ __align__(256) __half g_wq[(size_t)DM*DM];
__device__ __align__(256) __half g_wk[(size_t)DM*DM];
__device__ __align__(256) __half g_wv[(size_t)DM*DM];
__device__ __align__(256) __half g_wo[(size_t)DM*DM];
// Q,K fp16 [B,H,S,DH]; V fp16 transposed [B,H,DH,S]
__device__ __align__(256) __half g_qf[(size_t)MM*DM];
__device__ __align__(256) __half g_kf[(size_t)MM*DM];
__device__ __align__(256) __half g_vf[(size_t)MM*DM];
// ctx fp16 2-limb (written directly by flash epilogue)
__device__ __align__(256) __half g_ch[(size_t)MM*DM];
__device__ __align__(256) __half g_cl[(size_t)MM*DM];

// ---------------------------------------------------------------------------
// PTX helpers
// ---------------------------------------------------------------------------
__device__ __forceinline__ uint32_t smem_u32(const void* p) {
    uint32_t a;
    asm("{ .reg .u64 t; cvta.to.shared.u64 t, %1; cvt.u32.u64 %0, t; }"
        : "=r"(a) : "l"(p));
    return a;
}
__device__ __forceinline__ void cpa16(uint32_t s, const void* g) {
    asm volatile("cp.async.cg.shared.global [%0], [%1], 16;" :: "r"(s), "l"(g));
}
__device__ __forceinline__ void cpa_commit() {
    asm volatile("cp.async.commit_group;" ::: "memory");
}
__device__ __forceinline__ void ldmx4(uint32_t* r, uint32_t addr) {
    asm volatile("ldmatrix.sync.aligned.m8n8.x4.shared.b16 {%0,%1,%2,%3}, [%4];"
                 : "=r"(r[0]), "=r"(r[1]), "=r"(r[2]), "=r"(r[3]) : "r"(addr));
}
__device__ __forceinline__ void mmaf16(float* c, const uint32_t* a,
                                       uint32_t b0, uint32_t b1) {
    asm volatile(
        "mma.sync.aligned.m16n8k16.row.col.f32.f16.f16.f32 "
        "{%0,%1,%2,%3}, {%4,%5,%6,%7}, {%8,%9}, {%0,%1,%2,%3};"
        : "+f"(c[0]), "+f"(c[1]), "+f"(c[2]), "+f"(c[3])
        : "r"(a[0]), "r"(a[1]), "r"(a[2]), "r"(a[3]), "r"(b0), "r"(b1));
}
__device__ __forceinline__ uint32_t packh(float lo, float hi) {
    __half2 h = __floats2half2_rn(lo, hi);
    return *reinterpret_cast<uint32_t*>(&h);
}

// ---------------------------------------------------------------------------
// Split fp32 -> fp16 hi + fp16 lo (elementwise, x)
// ---------------------------------------------------------------------------
__global__ void split_kernel(const float* __restrict__ in,
                             __half* __restrict__ hi,
                             __half* __restrict__ lo, int n)
{
    int i = (blockIdx.x * blockDim.x + threadIdx.x) * 4;
    if (i >= n) return;
    float4 v = *(const float4*)(in + i);
    __half h0 = __float2half_rn(v.x);
    __half h1 = __float2half_rn(v.y);
    __half h2 = __float2half_rn(v.z);
    __half h3 = __float2half_rn(v.w);
    __half l0 = __float2half_rn(v.x - __half2float(h0));
    __half l1 = __float2half_rn(v.y - __half2float(h1));
    __half l2 = __float2half_rn(v.z - __half2float(h2));
    __half l3 = __float2half_rn(v.w - __half2float(h3));
    __half2 ph0; ph0.x = h0; ph0.y = h1;
    __half2 ph1; ph1.x = h2; ph1.y = h3;
    __half2 pl0; pl0.x = l0; pl0.y = l1;
    __half2 pl1; pl1.x = l2; pl1.y = l3;
    ((__half2*)(hi + i))[0] = ph0;
    ((__half2*)(hi + i))[1] = ph1;
    ((__half2*)(lo + i))[0] = pl0;
    ((__half2*)(lo + i))[1] = pl1;
}

// ---------------------------------------------------------------------------
// Transpose + fp16-quant weights: W[K,N] fp32 -> T[N,K] fp16
// ---------------------------------------------------------------------------
__global__ void whalfT_kernel(const float* __restrict__ W,
                              __half* __restrict__ T)
{
    __shared__ float t[32][33];
    int n0 = blockIdx.x * 32, k0 = blockIdx.y * 32;
    int tx = threadIdx.x, ty = threadIdx.y; // block (32, 8)
    #pragma unroll
    for (int i = 0; i < 32; i += 8)
        t[ty + i][tx] = W[(size_t)(k0 + ty + i) * DM + n0 + tx];
    __syncthreads();
    #pragma unroll
    for (int i = 0; i < 32; i += 8) {
        float v = t[tx][ty + i];   // = W[k0+tx][n0+ty+i]
        T[(size_t)(n0 + ty + i) * DM + k0 + tx] = __float2half_rn(v);
    }
}

// ---------------------------------------------------------------------------
// fp16 2-term GEMM: C = (Ah+Al)[M,K] @ W^T[N,K] + bias
// A near-exact fp16 2-limb, W single fp16. 128x128x32 tiles, 8 warps.
// MODE 0: fp32 out [M,N].  MODE 1: fp16 out [B,H,S,DH].
// MODE 2: fp16 out transposed [B,H,DH,S].
// ---------------------------------------------------------------------------
#define GBM 128
#define GBN 128
#define GBK 32
#define TILE_B (GBM * 40 * 2)  // 80B padded rows, 10240 B per matrix tile
#define STAGE_B (3 * TILE_B)   // Ah + Al + W
#define GEMM_SMEM (2 * STAGE_B)  // 61440
#define O_AH 0
#define O_AL TILE_B
#define O_W  (2 * TILE_B)

template<int MODE>
__global__ __launch_bounds__(256, 2)
void gemm_fp16_kernel(const __half* __restrict__ Ah,
                      const __half* __restrict__ Al,
                      const __half* __restrict__ W,
                      const float* __restrict__ bias,
                      float* __restrict__ C,
                      __half* __restrict__ Of)
{
    extern __shared__ char smem[];
    const uint32_t sbase = smem_u32(smem);
    const int tid = threadIdx.x;
    const int lane = tid & 31;
    const int wid = tid >> 5;
    const int wm = wid & 3;
    const int wn = wid >> 2;
    const int bm = blockIdx.y * GBM;
    const int bn = blockIdx.x * GBN;

    float acc[2][8][4];
    #pragma unroll
    for (int i = 0; i < 2; i++)
        #pragma unroll
        for (int j = 0; j < 8; j++)
            #pragma unroll
            for (int e = 0; e < 4; e++) acc[i][j][e] = 0.f;

    const int lrow = tid >> 1;
    const int lcol = (tid & 1) * 2;

    auto load_stage = [&](int buf, int k0) {
        uint32_t sb = sbase + buf * STAGE_B;
        uint32_t so0 = lrow * 80 + lcol * 16;
        uint32_t so1 = so0 + 16;
        size_t ga = (size_t)(bm + lrow) * DM + k0 + lcol * 8;
        size_t gw = (size_t)(bn + lrow) * DM + k0 + lcol * 8;
        cpa16(sb + O_AH + so0, Ah + ga);
        cpa16(sb + O_AH + so1, Ah + ga + 8);
        cpa16(sb + O_AL + so0, Al + ga);
        cpa16(sb + O_AL + so1, Al + ga + 8);
        cpa16(sb + O_W + so0, W + gw);
        cpa16(sb + O_W + so1, W + gw + 8);
    };

    const int a_row = (lane & 7) + ((lane >> 3) & 1) * 8;
    const int a_kh  = (lane >> 4) * 8;
    const int b_n   = (lane & 7) + ((lane >> 4) & 1) * 8;
    const int b_kh  = ((lane >> 3) & 1) * 8;

    const int T = DM / GBK;
    load_stage(0, 0);
    cpa_commit();

    for (int t = 0; t < T; t++) {
        if (t + 1 < T) {
            load_stage((t + 1) & 1, (t + 1) * GBK);
            cpa_commit();
            asm volatile("cp.async.wait_group 1;" ::: "memory");
        } else {
            asm volatile("cp.async.wait_group 0;" ::: "memory");
        }
        __syncthreads();

        const uint32_t sb = sbase + (t & 1) * STAGE_B;
        #pragma unroll
        for (int ks = 0; ks < 2; ks++) {
            uint32_t ah[2][4], al[2][4];
            #pragma unroll
            for (int mi = 0; mi < 2; mi++) {
                uint32_t ra = sb + (wm * 32 + mi * 16 + a_row) * 80
                            + (ks * 16 + a_kh) * 2;
                ldmx4(ah[mi], ra + O_AH);
                ldmx4(al[mi], ra + O_AL);
            }
            #pragma unroll
            for (int np = 0; np < 4; np++) {
                uint32_t wf[4];
                uint32_t rb = sb + (wn * 64 + np * 16 + b_n) * 80
                            + (ks * 16 + b_kh) * 2;
                ldmx4(wf, rb + O_W);
                #pragma unroll
                for (int mi = 0; mi < 2; mi++) {
                    mmaf16(acc[mi][np * 2 + 0], ah[mi], wf[0], wf[1]);
                    mmaf16(acc[mi][np * 2 + 1], ah[mi], wf[2], wf[3]);
                    mmaf16(acc[mi][np * 2 + 0], al[mi], wf[0], wf[1]);
                    mmaf16(acc[mi][np * 2 + 1], al[mi], wf[2], wf[3]);
                }
            }
        }
        __syncthreads();
    }

    // Epilogue
    #pragma unroll
    for (int mi = 0; mi < 2; mi++) {
        #pragma unroll
        for (int nf = 0; nf < 8; nf++) {
            int gcol = bn + wn * 64 + nf * 8 + (lane & 3) * 2;
            float b0 = __ldg(bias + gcol);
            float b1 = __ldg(bias + gcol + 1);
            #pragma unroll
            for (int half = 0; half < 2; half++) {
                int row = bm + wm * 32 + mi * 16 + (lane >> 2) + half * 8;
                float vx = acc[mi][nf][half * 2 + 0] + b0;
                float vy = acc[mi][nf][half * 2 + 1] + b1;
                if (MODE == 0) {
                    float2 v; v.x = vx; v.y = vy;
                    *(float2*)&C[(size_t)row * DM + gcol] = v;
                } else {
                    int hh = gcol >> 6, d = gcol & 63;
                    int b_ = row >> 11, s = row & 2047;
                    if (MODE == 1) {
                        size_t o = ((((size_t)b_ * HH + hh) * SS + s) * DH) + d;
                        __half2 hv = __floats2half2_rn(vx, vy);
                        *(__half2*)&Of[o] = hv;
                    } else {
                        size_t o = ((((size_t)b_ * HH + hh) * DH + d) * SS) + s;
                        Of[o] = __float2half_rn(vx);
                        Of[o + SS] = __float2half_rn(vy);
                    }
                }
            }
        }
    }
}

// ---------------------------------------------------------------------------
// Tensor-core flash attention, single-term fp16 QK and PV, fp32 softmax.
// 256 threads (8 warps x 16 q-rows), 64-key double-buffered chunks, 2 CTAs/SM.
// Epilogue writes ctx as fp16 hi/lo (row-major [MM, DM]).
// ---------------------------------------------------------------------------
#define FQSZ (128 * 144)           // 18432: Q tile, 144B padded rows
#define FKOFF 0
#define FVOFF (64 * 144)           // 9216
#define FSTAGE (2 * 64 * 144)      // 18432 per stage (K + V)
#define FLASH_SMEM (FQSZ + 2 * FSTAGE)  // 55296

__global__ __launch_bounds__(256, 2)
void flash_fp16_kernel(const __half* __restrict__ Qf,
                       const __half* __restrict__ Kf,
                       const __half* __restrict__ Vf,
                       __half* __restrict__ Ch,
                       __half* __restrict__ Cl)
{
    extern __shared__ char smem[];
    const uint32_t sbase = smem_u32(smem);
    const int tid = threadIdx.x;
    const int lane = tid & 31;
    const int wid = tid >> 5;              // 0..7
    const int bh = blockIdx.y;             // b*HH + h
    const int q0 = blockIdx.x * 128;

    const size_t qbase = ((size_t)bh * SS + q0) * DH;
    const size_t kbase = (size_t)bh * SS * DH;
    const size_t vbase = (size_t)bh * DH * SS;

    // ---- load Q tile (128 x 64 fp16): 1024 16B chunks ----
    #pragma unroll
    for (int i = 0; i < 4; i++) {
        int c = tid + i * 256;
        int row = c >> 3, col = c & 7;
        cpa16(sbase + row * 144 + col * 16, Qf + qbase + (size_t)row * DH + col * 8);
    }
    cpa_commit();

    auto load_kv = [&](int buf, int kv0) {
        uint32_t sb = sbase + FQSZ + buf * FSTAGE;
        #pragma unroll
        for (int i = 0; i < 2; i++) {
            int c = tid + i * 256;         // 512 chunks per matrix
            int row = c >> 3, col = c & 7;
            uint32_t so = row * 144 + col * 16;
            cpa16(sb + FKOFF + so, Kf + kbase + (size_t)(kv0 + row) * DH + col * 8);
            cpa16(sb + FVOFF + so, Vf + vbase + (size_t)row * SS + kv0 + col * 8);
        }
    };

    load_kv(0, 0);
    cpa_commit();
    asm volatile("cp.async.wait_group 0;" ::: "memory");
    __syncthreads();

    const int a_row = (lane & 7) + ((lane >> 3) & 1) * 8;
    const int a_kh  = (lane >> 4) * 8;
    const int b_n   = (lane & 7) + ((lane >> 4) & 1) * 8;
    const int b_kh  = ((lane >> 3) & 1) * 8;

    float Oa[8][4];
    #pragma unroll
    for (int j = 0; j < 8; j++)
        #pragma unroll
        for (int e = 0; e < 4; e++) Oa[j][e] = 0.f;
    float m0 = -1e30f, m1 = -1e30f, l0 = 0.f, l1 = 0.f;

    const int T = SS / 64;  // 32
    for (int t = 0; t < T; t++) {
        if (t + 1 < T) {
            load_kv((t + 1) & 1, (t + 1) * 64);
            cpa_commit();
            asm volatile("cp.async.wait_group 1;" ::: "memory");
        } else {
            asm volatile("cp.async.wait_group 0;" ::: "memory");
        }
        __syncthreads();

        const uint32_t sb = sbase + FQSZ + (t & 1) * FSTAGE;

        // ---- S = Q K^T (single fp16 term) ----
        float S[8][4];
        #pragma unroll
        for (int j = 0; j < 8; j++)
            #pragma unroll
            for (int e = 0; e < 4; e++) S[j][e] = 0.f;

        #pragma unroll
        for (int ks = 0; ks < 4; ks++) {
            uint32_t qf4[4];
            ldmx4(qf4, sbase + (wid * 16 + a_row) * 144 + (ks * 16 + a_kh) * 2);
            #pragma unroll
            for (int np = 0; np < 4; np++) {
                uint32_t kf4[4];
                ldmx4(kf4, sb + FKOFF + (np * 16 + b_n) * 144 + (ks * 16 + b_kh) * 2);
                mmaf16(S[np * 2 + 0], qf4, kf4[0], kf4[1]);
                mmaf16(S[np * 2 + 1], qf4, kf4[2], kf4[3]);
            }
        }

        // ---- online softmax ----
        float rx0 = -1e30f, rx1 = -1e30f;
        #pragma unroll
        for (int j = 0; j < 8; j++) {
            #pragma unroll
            for (int e = 0; e < 4; e++) S[j][e] *= 0.125f;
            rx0 = fmaxf(rx0, fmaxf(S[j][0], S[j][1]));
            rx1 = fmaxf(rx1, fmaxf(S[j][2], S[j][3]));
        }
        rx0 = fmaxf(rx0, __shfl_xor_sync(0xFFFFFFFF, rx0, 1));
        rx0 = fmaxf(rx0, __shfl_xor_sync(0xFFFFFFFF, rx0, 2));
        rx1 = fmaxf(rx1, __shfl_xor_sync(0xFFFFFFFF, rx1, 1));
        rx1 = fmaxf(rx1, __shfl_xor_sync(0xFFFFFFFF, rx1, 2));
        float mn0 = fmaxf(m0, rx0), mn1 = fmaxf(m1, rx1);
        float al0 = __expf(m0 - mn0), al1 = __expf(m1 - mn1);
        l0 *= al0; l1 *= al1;
        #pragma unroll
        for (int j = 0; j < 8; j++) {
            Oa[j][0] *= al0; Oa[j][1] *= al0;
            Oa[j][2] *= al1; Oa[j][3] *= al1;
        }
        #pragma unroll
        for (int j = 0; j < 8; j++) {
            S[j][0] = __expf(S[j][0] - mn0);
            S[j][1] = __expf(S[j][1] - mn0);
            S[j][2] = __expf(S[j][2] - mn1);
            S[j][3] = __expf(S[j][3] - mn1);
            l0 += S[j][0] + S[j][1];
            l1 += S[j][2] + S[j][3];
        }
        m0 = mn0; m1 = mn1;

        // ---- O += P V (single fp16 term) ----
        #pragma unroll
        for (int kc = 0; kc < 4; kc++) {
            uint32_t pa[4];
            #pragma unroll
            for (int u = 0; u < 2; u++) {
                const float* sp = S[kc * 2 + u];
                pa[u * 2 + 0] = packh(sp[0], sp[1]);
                pa[u * 2 + 1] = packh(sp[2], sp[3]);
            }
            #pragma unroll
            for (int np = 0; np < 4; np++) {
                uint32_t vf4[4];
                ldmx4(vf4, sb + FVOFF + (np * 16 + b_n) * 144 + (kc * 16 + b_kh) * 2);
                mmaf16(Oa[np * 2 + 0], pa, vf4[0], vf4[1]);
                mmaf16(Oa[np * 2 + 1], pa, vf4[2], vf4[3]);
            }
        }
        __syncthreads();
    }

    // ---- finalize: write ctx as fp16 hi/lo, row-major [MM, DM] ----
    l0 += __shfl_xor_sync(0xFFFFFFFF, l0, 1);
    l0 += __shfl_xor_sync(0xFFFFFFFF, l0, 2);
    l1 += __shfl_xor_sync(0xFFFFFFFF, l1, 1);
    l1 += __shfl_xor_sync(0xFFFFFFFF, l1, 2);
    float inv0 = 1.f / l0, inv1 = 1.f / l1;

    const int b_ = bh >> 4, h = bh & 15;
    const int r0 = q0 + wid * 16 + (lane >> 2);
    const int col = h * 64 + (lane & 3) * 2;
    #pragma unroll
    for (int nf = 0; nf < 8; nf++) {
        #pragma unroll
        for (int half = 0; half < 2; half++) {
            float inv = half ? inv1 : inv0;
            float vx = Oa[nf][half * 2 + 0] * inv;
            float vy = Oa[nf][half * 2 + 1] * inv;
            __half h0 = __float2half_rn(vx);
            __half h1 = __float2half_rn(vy);
            __half lo0 = __float2half_rn(vx - __half2float(h0));
            __half lo1 = __float2half_rn(vy - __half2float(h1));
            size_t o = ((size_t)b_ * SS + r0 + half * 8) * DM + col + nf * 8;
            __half2 ph; ph.x = h0; ph.y = h1;
            __half2 pl; pl.x = lo0; pl.y = lo1;
            *(__half2*)&Ch[o] = ph;
            *(__half2*)&Cl[o] = pl;
        }
    }
}

// ---------------------------------------------------------------------------
extern "C" void kernel_launch(void* const* d_in, const int* in_sizes, int n_in,
                              void* d_out, int out_size)
{
    const float* x  = (const float*)d_in[0];
    const float* wq = (const float*)d_in[1];
    const float* bq = (const float*)d_in[2];
    const float* wk = (const float*)d_in[3];
    const float* bk = (const float*)d_in[4];
    const float* wv = (const float*)d_in[5];
    const float* bv = (const float*)d_in[6];
    const float* wo = (const float*)d_in[7];
    const float* bo = (const float*)d_in[8];
    float* out = (float*)d_out;

    __half *xh, *xl, *wqp, *wkp, *wvp, *wop, *qf, *kf, *vf, *ch, *cl;
    cudaGetSymbolAddress((void**)&xh, g_xh);
    cudaGetSymbolAddress((void**)&xl, g_xl);
    cudaGetSymbolAddress((void**)&wqp, g_wq);
    cudaGetSymbolAddress((void**)&wkp, g_wk);
    cudaGetSymbolAddress((void**)&wvp, g_wv);
    cudaGetSymbolAddress((void**)&wop, g_wo);
    cudaGetSymbolAddress((void**)&qf, g_qf);
    cudaGetSymbolAddress((void**)&kf, g_kf);
    cudaGetSymbolAddress((void**)&vf, g_vf);
    cudaGetSymbolAddress((void**)&ch, g_ch);
    cudaGetSymbolAddress((void**)&cl, g_cl);

    cudaFuncSetAttribute(gemm_fp16_kernel<0>,
                         cudaFuncAttributeMaxDynamicSharedMemorySize, GEMM_SMEM);
    cudaFuncSetAttribute(gemm_fp16_kernel<1>,
                         cudaFuncAttributeMaxDynamicSharedMemorySize, GEMM_SMEM);
    cudaFuncSetAttribute(gemm_fp16_kernel<2>,
                         cudaFuncAttributeMaxDynamicSharedMemorySize, GEMM_SMEM);
    cudaFuncSetAttribute(flash_fp16_kernel,
                         cudaFuncAttributeMaxDynamicSharedMemorySize, FLASH_SMEM);

    // Split inputs
    const int NX = MM * DM;
    split_kernel<<<NX / (256 * 4), 256>>>(x, xh, xl, NX);
    dim3 wg(DM / 32, DM / 32), wb(32, 8);
    whalfT_kernel<<<wg, wb>>>(wq, wqp);
    whalfT_kernel<<<wg, wb>>>(wk, wkp);
    whalfT_kernel<<<wg, wb>>>(wv, wvp);
    whalfT_kernel<<<wg, wb>>>(wo, wop);

    // QKV projections (fp16 2-term) -> fp16 head layouts
    dim3 gg(DM / GBN, MM / GBM);  // (8, 32)
    gemm_fp16_kernel<1><<<gg, 256, GEMM_SMEM>>>(xh, xl, wqp, bq, nullptr, qf);
    gemm_fp16_kernel<1><<<gg, 256, GEMM_SMEM>>>(xh, xl, wkp, bk, nullptr, kf);
    gemm_fp16_kernel<2><<<gg, 256, GEMM_SMEM>>>(xh, xl, wvp, bv, nullptr, vf);

    // Tensor-core attention (fp16 single-term), writes ctx fp16 2-limb
    flash_fp16_kernel<<<dim3(SS / 128, BB * HH), 256, FLASH_SMEM>>>(
        qf, kf, vf, ch, cl);

    // Output projection (fp16 2-term)
    gemm_fp16_kernel<0><<<gg, 256, GEMM_SMEM>>>(ch, cl, wop, bo, out, nullptr);
}

// round 11
// speedup vs baseline: 3.6581x; 1.2872x over previous
#include <cuda_runtime.h>
#include <cuda_fp16.h>
#include <math.h>
#include <stdint.h>

#define BB 2
#define HH 16
#define SS 2048
#define DH 64
#define DM 1024
#define MM (BB*SS)   // 4096

// ---------------------------------------------------------------------------
// Scratch (device globals)
// ---------------------------------------------------------------------------
__device__ __align__(256) __half g_xf[(size_t)MM*DM];
__device__ __align__(256) __half g_wq[(size_t)DM*DM];
__device__ __align__(256) __half g_wk[(size_t)DM*DM];
__device__ __align__(256) __half g_wv[(size_t)DM*DM];
__device__ __align__(256) __half g_wo[(size_t)DM*DM];
// Q,K fp16 [B,H,S,DH]; V fp16 transposed [B,H,DH,S]
__device__ __align__(256) __half g_qf[(size_t)MM*DM];
__device__ __align__(256) __half g_kf[(size_t)MM*DM];
__device__ __align__(256) __half g_vf[(size_t)MM*DM];
// ctx fp16 (written directly by flash epilogue), row-major [MM, DM]
__device__ __align__(256) __half g_cf[(size_t)MM*DM];

// ---------------------------------------------------------------------------
// PTX helpers
// ---------------------------------------------------------------------------
__device__ __forceinline__ uint32_t smem_u32(const void* p) {
    uint32_t a;
    asm("{ .reg .u64 t; cvta.to.shared.u64 t, %1; cvt.u32.u64 %0, t; }"
        : "=r"(a) : "l"(p));
    return a;
}
__device__ __forceinline__ void cpa16(uint32_t s, const void* g) {
    asm volatile("cp.async.cg.shared.global [%0], [%1], 16;" :: "r"(s), "l"(g));
}
__device__ __forceinline__ void cpa_commit() {
    asm volatile("cp.async.commit_group;" ::: "memory");
}
__device__ __forceinline__ void ldmx4(uint32_t* r, uint32_t addr) {
    asm volatile("ldmatrix.sync.aligned.m8n8.x4.shared.b16 {%0,%1,%2,%3}, [%4];"
                 : "=r"(r[0]), "=r"(r[1]), "=r"(r[2]), "=r"(r[3]) : "r"(addr));
}
__device__ __forceinline__ void mmaf16(float* c, const uint32_t* a,
                                       uint32_t b0, uint32_t b1) {
    asm volatile(
        "mma.sync.aligned.m16n8k16.row.col.f32.f16.f16.f32 "
        "{%0,%1,%2,%3}, {%4,%5,%6,%7}, {%8,%9}, {%0,%1,%2,%3};"
        : "+f"(c[0]), "+f"(c[1]), "+f"(c[2]), "+f"(c[3])
        : "r"(a[0]), "r"(a[1]), "r"(a[2]), "r"(a[3]), "r"(b0), "r"(b1));
}
__device__ __forceinline__ uint32_t packh(float lo, float hi) {
    __half2 h = __floats2half2_rn(lo, hi);
    return *reinterpret_cast<uint32_t*>(&h);
}

// ---------------------------------------------------------------------------
// fp32 -> fp16 convert (x)
// ---------------------------------------------------------------------------
__global__ void tohalf_kernel(const float* __restrict__ in,
                              __half* __restrict__ out, int n)
{
    int i = (blockIdx.x * blockDim.x + threadIdx.x) * 4;
    if (i >= n) return;
    float4 v = *(const float4*)(in + i);
    __half2 h0 = __floats2half2_rn(v.x, v.y);
    __half2 h1 = __floats2half2_rn(v.z, v.w);
    ((__half2*)(out + i))[0] = h0;
    ((__half2*)(out + i))[1] = h1;
}

// ---------------------------------------------------------------------------
// Transpose + fp16-quant weights: W[K,N] fp32 -> T[N,K] fp16
// ---------------------------------------------------------------------------
__global__ void whalfT_kernel(const float* __restrict__ W,
                              __half* __restrict__ T)
{
    __shared__ float t[32][33];
    int n0 = blockIdx.x * 32, k0 = blockIdx.y * 32;
    int tx = threadIdx.x, ty = threadIdx.y; // block (32, 8)
    #pragma unroll
    for (int i = 0; i < 32; i += 8)
        t[ty + i][tx] = W[(size_t)(k0 + ty + i) * DM + n0 + tx];
    __syncthreads();
    #pragma unroll
    for (int i = 0; i < 32; i += 8) {
        float v = t[tx][ty + i];   // = W[k0+tx][n0+ty+i]
        T[(size_t)(n0 + ty + i) * DM + k0 + tx] = __float2half_rn(v);
    }
}

// ---------------------------------------------------------------------------
// fp16 single-term GEMM: C = A[M,K] @ W^T[N,K] + bias
// 128x128x32 tiles, 8 warps (4 M x 2 N), double-buffered cp.async.
// MODE 0: fp32 out [M,N].  MODE 1: fp16 out [B,H,S,DH].
// MODE 2: fp16 out transposed [B,H,DH,S].
// ---------------------------------------------------------------------------
#define GBM 128
#define GBN 128
#define GBK 32
#define TILE_B (GBM * 40 * 2)  // 80B padded rows, 10240 B per matrix tile
#define STAGE_B (2 * TILE_B)   // A + W
#define GEMM_SMEM (2 * STAGE_B)  // 40960
#define O_A 0
#define O_W TILE_B

template<int MODE>
__global__ __launch_bounds__(256, 2)
void gemm_fp16_kernel(const __half* __restrict__ A,
                      const __half* __restrict__ W,
                      const float* __restrict__ bias,
                      float* __restrict__ C,
                      __half* __restrict__ Of)
{
    extern __shared__ char smem[];
    const uint32_t sbase = smem_u32(smem);
    const int tid = threadIdx.x;
    const int lane = tid & 31;
    const int wid = tid >> 5;
    const int wm = wid & 3;
    const int wn = wid >> 2;
    const int bm = blockIdx.y * GBM;
    const int bn = blockIdx.x * GBN;

    float acc[2][8][4];
    #pragma unroll
    for (int i = 0; i < 2; i++)
        #pragma unroll
        for (int j = 0; j < 8; j++)
            #pragma unroll
            for (int e = 0; e < 4; e++) acc[i][j][e] = 0.f;

    const int lrow = tid >> 1;
    const int lcol = (tid & 1) * 2;

    auto load_stage = [&](int buf, int k0) {
        uint32_t sb = sbase + buf * STAGE_B;
        uint32_t so0 = lrow * 80 + lcol * 16;
        uint32_t so1 = so0 + 16;
        size_t ga = (size_t)(bm + lrow) * DM + k0 + lcol * 8;
        size_t gw = (size_t)(bn + lrow) * DM + k0 + lcol * 8;
        cpa16(sb + O_A + so0, A + ga);
        cpa16(sb + O_A + so1, A + ga + 8);
        cpa16(sb + O_W + so0, W + gw);
        cpa16(sb + O_W + so1, W + gw + 8);
    };

    const int a_row = (lane & 7) + ((lane >> 3) & 1) * 8;
    const int a_kh  = (lane >> 4) * 8;
    const int b_n   = (lane & 7) + ((lane >> 4) & 1) * 8;
    const int b_kh  = ((lane >> 3) & 1) * 8;

    const int T = DM / GBK;
    load_stage(0, 0);
    cpa_commit();

    for (int t = 0; t < T; t++) {
        if (t + 1 < T) {
            load_stage((t + 1) & 1, (t + 1) * GBK);
            cpa_commit();
            asm volatile("cp.async.wait_group 1;" ::: "memory");
        } else {
            asm volatile("cp.async.wait_group 0;" ::: "memory");
        }
        __syncthreads();

        const uint32_t sb = sbase + (t & 1) * STAGE_B;
        #pragma unroll
        for (int ks = 0; ks < 2; ks++) {
            uint32_t af[2][4];
            #pragma unroll
            for (int mi = 0; mi < 2; mi++) {
                uint32_t ra = sb + O_A + (wm * 32 + mi * 16 + a_row) * 80
                            + (ks * 16 + a_kh) * 2;
                ldmx4(af[mi], ra);
            }
            #pragma unroll
            for (int np = 0; np < 4; np++) {
                uint32_t wf[4];
                uint32_t rb = sb + O_W + (wn * 64 + np * 16 + b_n) * 80
                            + (ks * 16 + b_kh) * 2;
                ldmx4(wf, rb);
                #pragma unroll
                for (int mi = 0; mi < 2; mi++) {
                    mmaf16(acc[mi][np * 2 + 0], af[mi], wf[0], wf[1]);
                    mmaf16(acc[mi][np * 2 + 1], af[mi], wf[2], wf[3]);
                }
            }
        }
        __syncthreads();
    }

    // Epilogue
    #pragma unroll
    for (int mi = 0; mi < 2; mi++) {
        #pragma unroll
        for (int nf = 0; nf < 8; nf++) {
            int gcol = bn + wn * 64 + nf * 8 + (lane & 3) * 2;
            float b0 = __ldg(bias + gcol);
            float b1 = __ldg(bias + gcol + 1);
            #pragma unroll
            for (int half = 0; half < 2; half++) {
                int row = bm + wm * 32 + mi * 16 + (lane >> 2) + half * 8;
                float vx = acc[mi][nf][half * 2 + 0] + b0;
                float vy = acc[mi][nf][half * 2 + 1] + b1;
                if (MODE == 0) {
                    float2 v; v.x = vx; v.y = vy;
                    *(float2*)&C[(size_t)row * DM + gcol] = v;
                } else {
                    int hh = gcol >> 6, d = gcol & 63;
                    int b_ = row >> 11, s = row & 2047;
                    if (MODE == 1) {
                        size_t o = ((((size_t)b_ * HH + hh) * SS + s) * DH) + d;
                        __half2 hv = __floats2half2_rn(vx, vy);
                        *(__half2*)&Of[o] = hv;
                    } else {
                        size_t o = ((((size_t)b_ * HH + hh) * DH + d) * SS) + s;
                        Of[o] = __float2half_rn(vx);
                        Of[o + SS] = __float2half_rn(vy);
                    }
                }
            }
        }
    }
}

// ---------------------------------------------------------------------------
// Tensor-core flash attention, single-term fp16 QK and PV, fp32 softmax.
// 256 threads (8 warps x 16 q-rows), 64-key double-buffered chunks, 2 CTAs/SM.
// Epilogue writes ctx as single fp16 (row-major [MM, DM]).
// ---------------------------------------------------------------------------
#define FQSZ (128 * 144)           // 18432: Q tile, 144B padded rows
#define FKOFF 0
#define FVOFF (64 * 144)           // 9216
#define FSTAGE (2 * 64 * 144)      // 18432 per stage (K + V)
#define FLASH_SMEM (FQSZ + 2 * FSTAGE)  // 55296

__global__ __launch_bounds__(256, 2)
void flash_fp16_kernel(const __half* __restrict__ Qf,
                       const __half* __restrict__ Kf,
                       const __half* __restrict__ Vf,
                       __half* __restrict__ Cf)
{
    extern __shared__ char smem[];
    const uint32_t sbase = smem_u32(smem);
    const int tid = threadIdx.x;
    const int lane = tid & 31;
    const int wid = tid >> 5;              // 0..7
    const int bh = blockIdx.y;             // b*HH + h
    const int q0 = blockIdx.x * 128;

    const size_t qbase = ((size_t)bh * SS + q0) * DH;
    const size_t kbase = (size_t)bh * SS * DH;
    const size_t vbase = (size_t)bh * DH * SS;

    // ---- load Q tile (128 x 64 fp16): 1024 16B chunks ----
    #pragma unroll
    for (int i = 0; i < 4; i++) {
        int c = tid + i * 256;
        int row = c >> 3, col = c & 7;
        cpa16(sbase + row * 144 + col * 16, Qf + qbase + (size_t)row * DH + col * 8);
    }
    cpa_commit();

    auto load_kv = [&](int buf, int kv0) {
        uint32_t sb = sbase + FQSZ + buf * FSTAGE;
        #pragma unroll
        for (int i = 0; i < 2; i++) {
            int c = tid + i * 256;         // 512 chunks per matrix
            int row = c >> 3, col = c & 7;
            uint32_t so = row * 144 + col * 16;
            cpa16(sb + FKOFF + so, Kf + kbase + (size_t)(kv0 + row) * DH + col * 8);
            cpa16(sb + FVOFF + so, Vf + vbase + (size_t)row * SS + kv0 + col * 8);
        }
    };

    load_kv(0, 0);
    cpa_commit();
    asm volatile("cp.async.wait_group 0;" ::: "memory");
    __syncthreads();

    const int a_row = (lane & 7) + ((lane >> 3) & 1) * 8;
    const int a_kh  = (lane >> 4) * 8;
    const int b_n   = (lane & 7) + ((lane >> 4) & 1) * 8;
    const int b_kh  = ((lane >> 3) & 1) * 8;

    float Oa[8][4];
    #pragma unroll
    for (int j = 0; j < 8; j++)
        #pragma unroll
        for (int e = 0; e < 4; e++) Oa[j][e] = 0.f;
    float m0 = -1e30f, m1 = -1e30f, l0 = 0.f, l1 = 0.f;

    const int T = SS / 64;  // 32
    for (int t = 0; t < T; t++) {
        if (t + 1 < T) {
            load_kv((t + 1) & 1, (t + 1) * 64);
            cpa_commit();
            asm volatile("cp.async.wait_group 1;" ::: "memory");
        } else {
            asm volatile("cp.async.wait_group 0;" ::: "memory");
        }
        __syncthreads();

        const uint32_t sb = sbase + FQSZ + (t & 1) * FSTAGE;

        // ---- S = Q K^T ----
        float S[8][4];
        #pragma unroll
        for (int j = 0; j < 8; j++)
            #pragma unroll
            for (int e = 0; e < 4; e++) S[j][e] = 0.f;

        #pragma unroll
        for (int ks = 0; ks < 4; ks++) {
            uint32_t qf4[4];
            ldmx4(qf4, sbase + (wid * 16 + a_row) * 144 + (ks * 16 + a_kh) * 2);
            #pragma unroll
            for (int np = 0; np < 4; np++) {
                uint32_t kf4[4];
                ldmx4(kf4, sb + FKOFF + (np * 16 + b_n) * 144 + (ks * 16 + b_kh) * 2);
                mmaf16(S[np * 2 + 0], qf4, kf4[0], kf4[1]);
                mmaf16(S[np * 2 + 1], qf4, kf4[2], kf4[3]);
            }
        }

        // ---- online softmax ----
        float rx0 = -1e30f, rx1 = -1e30f;
        #pragma unroll
        for (int j = 0; j < 8; j++) {
            #pragma unroll
            for (int e = 0; e < 4; e++) S[j][e] *= 0.125f;
            rx0 = fmaxf(rx0, fmaxf(S[j][0], S[j][1]));
            rx1 = fmaxf(rx1, fmaxf(S[j][2], S[j][3]));
        }
        rx0 = fmaxf(rx0, __shfl_xor_sync(0xFFFFFFFF, rx0, 1));
        rx0 = fmaxf(rx0, __shfl_xor_sync(0xFFFFFFFF, rx0, 2));
        rx1 = fmaxf(rx1, __shfl_xor_sync(0xFFFFFFFF, rx1, 1));
        rx1 = fmaxf(rx1, __shfl_xor_sync(0xFFFFFFFF, rx1, 2));
        float mn0 = fmaxf(m0, rx0), mn1 = fmaxf(m1, rx1);
        float al0 = __expf(m0 - mn0), al1 = __expf(m1 - mn1);
        l0 *= al0; l1 *= al1;
        #pragma unroll
        for (int j = 0; j < 8; j++) {
            Oa[j][0] *= al0; Oa[j][1] *= al0;
            Oa[j][2] *= al1; Oa[j][3] *= al1;
        }
        #pragma unroll
        for (int j = 0; j < 8; j++) {
            S[j][0] = __expf(S[j][0] - mn0);
            S[j][1] = __expf(S[j][1] - mn0);
            S[j][2] = __expf(S[j][2] - mn1);
            S[j][3] = __expf(S[j][3] - mn1);
            l0 += S[j][0] + S[j][1];
            l1 += S[j][2] + S[j][3];
        }
        m0 = mn0; m1 = mn1;

        // ---- O += P V ----
        #pragma unroll
        for (int kc = 0; kc < 4; kc++) {
            uint32_t pa[4];
            #pragma unroll
            for (int u = 0; u < 2; u++) {
                const float* sp = S[kc * 2 + u];
                pa[u * 2 + 0] = packh(sp[0], sp[1]);
                pa[u * 2 + 1] = packh(sp[2], sp[3]);
            }
            #pragma unroll
            for (int np = 0; np < 4; np++) {
                uint32_t vf4[4];
                ldmx4(vf4, sb + FVOFF + (np * 16 + b_n) * 144 + (kc * 16 + b_kh) * 2);
                mmaf16(Oa[np * 2 + 0], pa, vf4[0], vf4[1]);
                mmaf16(Oa[np * 2 + 1], pa, vf4[2], vf4[3]);
            }
        }
        __syncthreads();
    }

    // ---- finalize: write ctx as fp16, row-major [MM, DM] ----
    l0 += __shfl_xor_sync(0xFFFFFFFF, l0, 1);
    l0 += __shfl_xor_sync(0xFFFFFFFF, l0, 2);
    l1 += __shfl_xor_sync(0xFFFFFFFF, l1, 1);
    l1 += __shfl_xor_sync(0xFFFFFFFF, l1, 2);
    float inv0 = 1.f / l0, inv1 = 1.f / l1;

    const int b_ = bh >> 4, h = bh & 15;
    const int r0 = q0 + wid * 16 + (lane >> 2);
    const int col = h * 64 + (lane & 3) * 2;
    #pragma unroll
    for (int nf = 0; nf < 8; nf++) {
        #pragma unroll
        for (int half = 0; half < 2; half++) {
            float inv = half ? inv1 : inv0;
            float vx = Oa[nf][half * 2 + 0] * inv;
            float vy = Oa[nf][half * 2 + 1] * inv;
            size_t o = ((size_t)b_ * SS + r0 + half * 8) * DM + col + nf * 8;
            __half2 hv = __floats2half2_rn(vx, vy);
            *(__half2*)&Cf[o] = hv;
        }
    }
}

// ---------------------------------------------------------------------------
extern "C" void kernel_launch(void* const* d_in, const int* in_sizes, int n_in,
                              void* d_out, int out_size)
{
    const float* x  = (const float*)d_in[0];
    const float* wq = (const float*)d_in[1];
    const float* bq = (const float*)d_in[2];
    const float* wk = (const float*)d_in[3];
    const float* bk = (const float*)d_in[4];
    const float* wv = (const float*)d_in[5];
    const float* bv = (const float*)d_in[6];
    const float* wo = (const float*)d_in[7];
    const float* bo = (const float*)d_in[8];
    float* out = (float*)d_out;

    __half *xf, *wqp, *wkp, *wvp, *wop, *qf, *kf, *vf, *cf;
    cudaGetSymbolAddress((void**)&xf, g_xf);
    cudaGetSymbolAddress((void**)&wqp, g_wq);
    cudaGetSymbolAddress((void**)&wkp, g_wk);
    cudaGetSymbolAddress((void**)&wvp, g_wv);
    cudaGetSymbolAddress((void**)&wop, g_wo);
    cudaGetSymbolAddress((void**)&qf, g_qf);
    cudaGetSymbolAddress((void**)&kf, g_kf);
    cudaGetSymbolAddress((void**)&vf, g_vf);
    cudaGetSymbolAddress((void**)&cf, g_cf);

    cudaFuncSetAttribute(gemm_fp16_kernel<0>,
                         cudaFuncAttributeMaxDynamicSharedMemorySize, GEMM_SMEM);
    cudaFuncSetAttribute(gemm_fp16_kernel<1>,
                         cudaFuncAttributeMaxDynamicSharedMemorySize, GEMM_SMEM);
    cudaFuncSetAttribute(gemm_fp16_kernel<2>,
                         cudaFuncAttributeMaxDynamicSharedMemorySize, GEMM_SMEM);
    cudaFuncSetAttribute(flash_fp16_kernel,
                         cudaFuncAttributeMaxDynamicSharedMemorySize, FLASH_SMEM);

    // Convert inputs
    const int NX = MM * DM;
    tohalf_kernel<<<NX / 1024, 256>>>(x, xf, NX);
    dim3 wg(DM / 32, DM / 32), wb(32, 8);
    whalfT_kernel<<<wg, wb>>>(wq, wqp);
    whalfT_kernel<<<wg, wb>>>(wk, wkp);
    whalfT_kernel<<<wg, wb>>>(wv, wvp);
    whalfT_kernel<<<wg, wb>>>(wo, wop);

    // QKV projections (fp16 single-term) -> fp16 head layouts
    dim3 gg(DM / GBN, MM / GBM);  // (8, 32)
    gemm_fp16_kernel<1><<<gg, 256, GEMM_SMEM>>>(xf, wqp, bq, nullptr, qf);
    gemm_fp16_kernel<1><<<gg, 256, GEMM_SMEM>>>(xf, wkp, bk, nullptr, kf);
    gemm_fp16_kernel<2><<<gg, 256, GEMM_SMEM>>>(xf, wvp, bv, nullptr, vf);

    // Tensor-core attention (fp16 single-term), writes ctx fp16
    flash_fp16_kernel<<<dim3(SS / 128, BB * HH), 256, FLASH_SMEM>>>(
        qf, kf, vf, cf);

    // Output projection (fp16 single-term)
    gemm_fp16_kernel<0><<<gg, 256, GEMM_SMEM>>>(cf, wop, bo, out, nullptr);
}

// round 12
// speedup vs baseline: 3.8509x; 1.0527x over previous
#include <cuda_runtime.h>
#include <cuda_fp16.h>
#include <math.h>
#include <stdint.h>

#define BB 2
#define HH 16
#define SS 2048
#define DH 64
#define DM 1024
#define MM (BB*SS)   // 4096

// ---------------------------------------------------------------------------
// Scratch (device globals)
// ---------------------------------------------------------------------------
__device__ __align__(256) __half g_xf[(size_t)MM*DM];
__device__ __align__(256) __half g_w4[4][(size_t)DM*DM];  // wq,wk,wv,wo [N,K]
// Q,K fp16 [B,H,S,DH] (Q pre-scaled by 1/8); V fp16 transposed [B,H,DH,S]
__device__ __align__(256) __half g_qf[(size_t)MM*DM];
__device__ __align__(256) __half g_kf[(size_t)MM*DM];
__device__ __align__(256) __half g_vf[(size_t)MM*DM];
// ctx fp16 (flash epilogue), row-major [MM, DM]
__device__ __align__(256) __half g_cf[(size_t)MM*DM];

// ---------------------------------------------------------------------------
// PTX helpers
// ---------------------------------------------------------------------------
__device__ __forceinline__ uint32_t smem_u32(const void* p) {
    uint32_t a;
    asm("{ .reg .u64 t; cvta.to.shared.u64 t, %1; cvt.u32.u64 %0, t; }"
        : "=r"(a) : "l"(p));
    return a;
}
__device__ __forceinline__ void cpa16(uint32_t s, const void* g) {
    asm volatile("cp.async.cg.shared.global [%0], [%1], 16;" :: "r"(s), "l"(g));
}
__device__ __forceinline__ void cpa_commit() {
    asm volatile("cp.async.commit_group;" ::: "memory");
}
__device__ __forceinline__ void ldmx4(uint32_t* r, uint32_t addr) {
    asm volatile("ldmatrix.sync.aligned.m8n8.x4.shared.b16 {%0,%1,%2,%3}, [%4];"
                 : "=r"(r[0]), "=r"(r[1]), "=r"(r[2]), "=r"(r[3]) : "r"(addr));
}
__device__ __forceinline__ void mmaf16(float* c, const uint32_t* a,
                                       uint32_t b0, uint32_t b1) {
    asm volatile(
        "mma.sync.aligned.m16n8k16.row.col.f32.f16.f16.f32 "
        "{%0,%1,%2,%3}, {%4,%5,%6,%7}, {%8,%9}, {%0,%1,%2,%3};"
        : "+f"(c[0]), "+f"(c[1]), "+f"(c[2]), "+f"(c[3])
        : "r"(a[0]), "r"(a[1]), "r"(a[2]), "r"(a[3]), "r"(b0), "r"(b1));
}
__device__ __forceinline__ uint32_t packh(float lo, float hi) {
    __half2 h = __floats2half2_rn(lo, hi);
    return *reinterpret_cast<uint32_t*>(&h);
}

// ---------------------------------------------------------------------------
// Fused prep: blocks [0,4096): x fp32->fp16; [4096,8192): weight transpose.
// ---------------------------------------------------------------------------
__global__ void prep_kernel(const float* __restrict__ x,
                            const float* __restrict__ wq,
                            const float* __restrict__ wk,
                            const float* __restrict__ wv,
                            const float* __restrict__ wo)
{
    int b = blockIdx.x;
    if (b < 4096) {
        int i = (b * 256 + threadIdx.x) * 4;
        float4 v = *(const float4*)(x + i);
        __half2 h0 = __floats2half2_rn(v.x, v.y);
        __half2 h1 = __floats2half2_rn(v.z, v.w);
        ((__half2*)(g_xf + i))[0] = h0;
        ((__half2*)(g_xf + i))[1] = h1;
        return;
    }
    __shared__ float t[32][33];
    int r = b - 4096;
    int w = r >> 10;                  // which weight
    int tl = r & 1023;
    int n0 = (tl & 31) * 32, k0 = (tl >> 5) * 32;
    const float* W = (w == 0) ? wq : (w == 1) ? wk : (w == 2) ? wv : wo;
    __half* T = g_w4[w];
    int tx = threadIdx.x & 31, ty = threadIdx.x >> 5;  // (32, 8)
    #pragma unroll
    for (int i = 0; i < 32; i += 8)
        t[ty + i][tx] = W[(size_t)(k0 + ty + i) * DM + n0 + tx];
    __syncthreads();
    #pragma unroll
    for (int i = 0; i < 32; i += 8) {
        float v = t[tx][ty + i];      // W[k0+tx][n0+ty+i]
        T[(size_t)(n0 + ty + i) * DM + k0 + tx] = __float2half_rn(v);
    }
}

// ---------------------------------------------------------------------------
// fp16 single-term GEMM core (shared by fused-QKV and outproj kernels)
// 128x128x32 tiles, 8 warps (4 M x 2 N), double-buffered cp.async.
// ---------------------------------------------------------------------------
#define GBM 128
#define GBN 128
#define GBK 32
#define TILE_B (GBM * 40 * 2)
#define STAGE_B (2 * TILE_B)
#define GEMM_SMEM (2 * STAGE_B)  // 40960
#define O_A 0
#define O_W TILE_B

struct GemmAcc { float a[2][8][4]; };

__device__ __forceinline__ void gemm_mainloop(const __half* __restrict__ A,
                                              const __half* __restrict__ W,
                                              int bm, int bn, char* smem,
                                              GemmAcc& acc)
{
    const uint32_t sbase = smem_u32(smem);
    const int tid = threadIdx.x;
    const int lane = tid & 31;
    const int wid = tid >> 5;
    const int wm = wid & 3;
    const int wn = wid >> 2;

    #pragma unroll
    for (int i = 0; i < 2; i++)
        #pragma unroll
        for (int j = 0; j < 8; j++)
            #pragma unroll
            for (int e = 0; e < 4; e++) acc.a[i][j][e] = 0.f;

    const int lrow = tid >> 1;
    const int lcol = (tid & 1) * 2;

    auto load_stage = [&](int buf, int k0) {
        uint32_t sb = sbase + buf * STAGE_B;
        uint32_t so0 = lrow * 80 + lcol * 16;
        uint32_t so1 = so0 + 16;
        size_t ga = (size_t)(bm + lrow) * DM + k0 + lcol * 8;
        size_t gw = (size_t)(bn + lrow) * DM + k0 + lcol * 8;
        cpa16(sb + O_A + so0, A + ga);
        cpa16(sb + O_A + so1, A + ga + 8);
        cpa16(sb + O_W + so0, W + gw);
        cpa16(sb + O_W + so1, W + gw + 8);
    };

    const int a_row = (lane & 7) + ((lane >> 3) & 1) * 8;
    const int a_kh  = (lane >> 4) * 8;
    const int b_n   = (lane & 7) + ((lane >> 4) & 1) * 8;
    const int b_kh  = ((lane >> 3) & 1) * 8;

    const int T = DM / GBK;
    load_stage(0, 0);
    cpa_commit();

    for (int t = 0; t < T; t++) {
        if (t + 1 < T) {
            load_stage((t + 1) & 1, (t + 1) * GBK);
            cpa_commit();
            asm volatile("cp.async.wait_group 1;" ::: "memory");
        } else {
            asm volatile("cp.async.wait_group 0;" ::: "memory");
        }
        __syncthreads();

        const uint32_t sb = sbase + (t & 1) * STAGE_B;
        #pragma unroll
        for (int ks = 0; ks < 2; ks++) {
            uint32_t af[2][4];
            #pragma unroll
            for (int mi = 0; mi < 2; mi++) {
                uint32_t ra = sb + O_A + (wm * 32 + mi * 16 + a_row) * 80
                            + (ks * 16 + a_kh) * 2;
                ldmx4(af[mi], ra);
            }
            #pragma unroll
            for (int np = 0; np < 4; np++) {
                uint32_t wf[4];
                uint32_t rb = sb + O_W + (wn * 64 + np * 16 + b_n) * 80
                            + (ks * 16 + b_kh) * 2;
                ldmx4(wf, rb);
                #pragma unroll
                for (int mi = 0; mi < 2; mi++) {
                    mmaf16(acc.a[mi][np * 2 + 0], af[mi], wf[0], wf[1]);
                    mmaf16(acc.a[mi][np * 2 + 1], af[mi], wf[2], wf[3]);
                }
            }
        }
        __syncthreads();
    }
}

// Fused QKV projection: blockIdx.z selects weight/bias/output.
// z=0: Q (scaled by 0.125) -> [B,H,S,DH]; z=1: K -> [B,H,S,DH];
// z=2: V -> [B,H,DH,S] transposed.
__global__ __launch_bounds__(256, 2)
void gemm_qkv_kernel(const float* __restrict__ bq,
                     const float* __restrict__ bk,
                     const float* __restrict__ bv)
{
    extern __shared__ char smem[];
    const int z = blockIdx.z;
    const int bm = blockIdx.y * GBM;
    const int bn = blockIdx.x * GBN;
    const float* bias = (z == 0) ? bq : (z == 1) ? bk : bv;
    __half* Of = (z == 0) ? g_qf : (z == 1) ? g_kf : g_vf;
    const float qs = (z == 0) ? 0.125f : 1.f;

    GemmAcc acc;
    gemm_mainloop(g_xf, g_w4[z], bm, bn, smem, acc);

    const int lane = threadIdx.x & 31;
    const int wid = threadIdx.x >> 5;
    const int wm = wid & 3;
    const int wn = wid >> 2;

    #pragma unroll
    for (int mi = 0; mi < 2; mi++) {
        #pragma unroll
        for (int nf = 0; nf < 8; nf++) {
            int gcol = bn + wn * 64 + nf * 8 + (lane & 3) * 2;
            float b0 = __ldg(bias + gcol);
            float b1 = __ldg(bias + gcol + 1);
            #pragma unroll
            for (int half = 0; half < 2; half++) {
                int row = bm + wm * 32 + mi * 16 + (lane >> 2) + half * 8;
                float vx = (acc.a[mi][nf][half * 2 + 0] + b0) * qs;
                float vy = (acc.a[mi][nf][half * 2 + 1] + b1) * qs;
                int hh = gcol >> 6, d = gcol & 63;
                int b_ = row >> 11, s = row & 2047;
                if (z != 2) {
                    size_t o = ((((size_t)b_ * HH + hh) * SS + s) * DH) + d;
                    __half2 hv = __floats2half2_rn(vx, vy);
                    *(__half2*)&Of[o] = hv;
                } else {
                    size_t o = ((((size_t)b_ * HH + hh) * DH + d) * SS) + s;
                    Of[o] = __float2half_rn(vx);
                    Of[o + SS] = __float2half_rn(vy);
                }
            }
        }
    }
}

// Output projection: ctx(fp16) @ wo^T + bo -> fp32 out
__global__ __launch_bounds__(256, 2)
void gemm_out_kernel(const float* __restrict__ bias, float* __restrict__ C)
{
    extern __shared__ char smem[];
    const int bm = blockIdx.y * GBM;
    const int bn = blockIdx.x * GBN;

    GemmAcc acc;
    gemm_mainloop(g_cf, g_w4[3], bm, bn, smem, acc);

    const int lane = threadIdx.x & 31;
    const int wid = threadIdx.x >> 5;
    const int wm = wid & 3;
    const int wn = wid >> 2;

    #pragma unroll
    for (int mi = 0; mi < 2; mi++) {
        #pragma unroll
        for (int nf = 0; nf < 8; nf++) {
            int gcol = bn + wn * 64 + nf * 8 + (lane & 3) * 2;
            float b0 = __ldg(bias + gcol);
            float b1 = __ldg(bias + gcol + 1);
            #pragma unroll
            for (int half = 0; half < 2; half++) {
                int row = bm + wm * 32 + mi * 16 + (lane >> 2) + half * 8;
                float2 v;
                v.x = acc.a[mi][nf][half * 2 + 0] + b0;
                v.y = acc.a[mi][nf][half * 2 + 1] + b1;
                *(float2*)&C[(size_t)row * DM + gcol] = v;
            }
        }
    }
}

// ---------------------------------------------------------------------------
// Tensor-core flash attention, fp16 QK and PV, fp32 softmax.
// Q pre-scaled by 1/8 (folded into projection). Rescale skipped when the
// running max is unchanged. 256 thr, 64-key double-buffered, 2 CTAs/SM.
// ---------------------------------------------------------------------------
#define FQSZ (128 * 144)
#define FKOFF 0
#define FVOFF (64 * 144)
#define FSTAGE (2 * 64 * 144)
#define FLASH_SMEM (FQSZ + 2 * FSTAGE)  // 55296

__global__ __launch_bounds__(256, 2)
void flash_fp16_kernel()
{
    extern __shared__ char smem[];
    const uint32_t sbase = smem_u32(smem);
    const int tid = threadIdx.x;
    const int lane = tid & 31;
    const int wid = tid >> 5;
    const int bh = blockIdx.y;
    const int q0 = blockIdx.x * 128;

    const size_t qbase = ((size_t)bh * SS + q0) * DH;
    const size_t kbase = (size_t)bh * SS * DH;
    const size_t vbase = (size_t)bh * DH * SS;

    #pragma unroll
    for (int i = 0; i < 4; i++) {
        int c = tid + i * 256;
        int row = c >> 3, col = c & 7;
        cpa16(sbase + row * 144 + col * 16,
              g_qf + qbase + (size_t)row * DH + col * 8);
    }
    cpa_commit();

    auto load_kv = [&](int buf, int kv0) {
        uint32_t sb = sbase + FQSZ + buf * FSTAGE;
        #pragma unroll
        for (int i = 0; i < 2; i++) {
            int c = tid + i * 256;
            int row = c >> 3, col = c & 7;
            uint32_t so = row * 144 + col * 16;
            cpa16(sb + FKOFF + so, g_kf + kbase + (size_t)(kv0 + row) * DH + col * 8);
            cpa16(sb + FVOFF + so, g_vf + vbase + (size_t)row * SS + kv0 + col * 8);
        }
    };

    load_kv(0, 0);
    cpa_commit();
    asm volatile("cp.async.wait_group 0;" ::: "memory");
    __syncthreads();

    const int a_row = (lane & 7) + ((lane >> 3) & 1) * 8;
    const int a_kh  = (lane >> 4) * 8;
    const int b_n   = (lane & 7) + ((lane >> 4) & 1) * 8;
    const int b_kh  = ((lane >> 3) & 1) * 8;

    float Oa[8][4];
    #pragma unroll
    for (int j = 0; j < 8; j++)
        #pragma unroll
        for (int e = 0; e < 4; e++) Oa[j][e] = 0.f;
    float m0 = -1e30f, m1 = -1e30f, l0 = 0.f, l1 = 0.f;

    const int T = SS / 64;
    for (int t = 0; t < T; t++) {
        if (t + 1 < T) {
            load_kv((t + 1) & 1, (t + 1) * 64);
            cpa_commit();
            asm volatile("cp.async.wait_group 1;" ::: "memory");
        } else {
            asm volatile("cp.async.wait_group 0;" ::: "memory");
        }
        __syncthreads();

        const uint32_t sb = sbase + FQSZ + (t & 1) * FSTAGE;

        // ---- S = Q K^T (Q pre-scaled) ----
        float S[8][4];
        #pragma unroll
        for (int j = 0; j < 8; j++)
            #pragma unroll
            for (int e = 0; e < 4; e++) S[j][e] = 0.f;

        #pragma unroll
        for (int ks = 0; ks < 4; ks++) {
            uint32_t qf4[4];
            ldmx4(qf4, sbase + (wid * 16 + a_row) * 144 + (ks * 16 + a_kh) * 2);
            #pragma unroll
            for (int np = 0; np < 4; np++) {
                uint32_t kf4[4];
                ldmx4(kf4, sb + FKOFF + (np * 16 + b_n) * 144 + (ks * 16 + b_kh) * 2);
                mmaf16(S[np * 2 + 0], qf4, kf4[0], kf4[1]);
                mmaf16(S[np * 2 + 1], qf4, kf4[2], kf4[3]);
            }
        }

        // ---- online softmax ----
        float rx0 = -1e30f, rx1 = -1e30f;
        #pragma unroll
        for (int j = 0; j < 8; j++) {
            rx0 = fmaxf(rx0, fmaxf(S[j][0], S[j][1]));
            rx1 = fmaxf(rx1, fmaxf(S[j][2], S[j][3]));
        }
        rx0 = fmaxf(rx0, __shfl_xor_sync(0xFFFFFFFF, rx0, 1));
        rx0 = fmaxf(rx0, __shfl_xor_sync(0xFFFFFFFF, rx0, 2));
        rx1 = fmaxf(rx1, __shfl_xor_sync(0xFFFFFFFF, rx1, 1));
        rx1 = fmaxf(rx1, __shfl_xor_sync(0xFFFFFFFF, rx1, 2));
        float mn0 = fmaxf(m0, rx0), mn1 = fmaxf(m1, rx1);
        if (mn0 != m0 || mn1 != m1) {
            float al0 = __expf(m0 - mn0), al1 = __expf(m1 - mn1);
            l0 *= al0; l1 *= al1;
            #pragma unroll
            for (int j = 0; j < 8; j++) {
                Oa[j][0] *= al0; Oa[j][1] *= al0;
                Oa[j][2] *= al1; Oa[j][3] *= al1;
            }
            m0 = mn0; m1 = mn1;
        }
        #pragma unroll
        for (int j = 0; j < 8; j++) {
            S[j][0] = __expf(S[j][0] - m0);
            S[j][1] = __expf(S[j][1] - m0);
            S[j][2] = __expf(S[j][2] - m1);
            S[j][3] = __expf(S[j][3] - m1);
            l0 += S[j][0] + S[j][1];
            l1 += S[j][2] + S[j][3];
        }

        // ---- O += P V ----
        #pragma unroll
        for (int kc = 0; kc < 4; kc++) {
            uint32_t pa[4];
            #pragma unroll
            for (int u = 0; u < 2; u++) {
                const float* sp = S[kc * 2 + u];
                pa[u * 2 + 0] = packh(sp[0], sp[1]);
                pa[u * 2 + 1] = packh(sp[2], sp[3]);
            }
            #pragma unroll
            for (int np = 0; np < 4; np++) {
                uint32_t vf4[4];
                ldmx4(vf4, sb + FVOFF + (np * 16 + b_n) * 144 + (kc * 16 + b_kh) * 2);
                mmaf16(Oa[np * 2 + 0], pa, vf4[0], vf4[1]);
                mmaf16(Oa[np * 2 + 1], pa, vf4[2], vf4[3]);
            }
        }
        __syncthreads();
    }

    // ---- finalize ----
    l0 += __shfl_xor_sync(0xFFFFFFFF, l0, 1);
    l0 += __shfl_xor_sync(0xFFFFFFFF, l0, 2);
    l1 += __shfl_xor_sync(0xFFFFFFFF, l1, 1);
    l1 += __shfl_xor_sync(0xFFFFFFFF, l1, 2);
    float inv0 = 1.f / l0, inv1 = 1.f / l1;

    const int b_ = bh >> 4, h = bh & 15;
    const int r0 = q0 + wid * 16 + (lane >> 2);
    const int col = h * 64 + (lane & 3) * 2;
    #pragma unroll
    for (int nf = 0; nf < 8; nf++) {
        #pragma unroll
        for (int half = 0; half < 2; half++) {
            float inv = half ? inv1 : inv0;
            float vx = Oa[nf][half * 2 + 0] * inv;
            float vy = Oa[nf][half * 2 + 1] * inv;
            size_t o = ((size_t)b_ * SS + r0 + half * 8) * DM + col + nf * 8;
            __half2 hv = __floats2half2_rn(vx, vy);
            *(__half2*)&g_cf[o] = hv;
        }
    }
}

// ---------------------------------------------------------------------------
extern "C" void kernel_launch(void* const* d_in, const int* in_sizes, int n_in,
                              void* d_out, int out_size)
{
    const float* x  = (const float*)d_in[0];
    const float* wq = (const float*)d_in[1];
    const float* bq = (const float*)d_in[2];
    const float* wk = (const float*)d_in[3];
    const float* bk = (const float*)d_in[4];
    const float* wv = (const float*)d_in[5];
    const float* bv = (const float*)d_in[6];
    const float* wo = (const float*)d_in[7];
    const float* bo = (const float*)d_in[8];
    float* out = (float*)d_out;

    cudaFuncSetAttribute(gemm_qkv_kernel,
                         cudaFuncAttributeMaxDynamicSharedMemorySize, GEMM_SMEM);
    cudaFuncSetAttribute(gemm_out_kernel,
                         cudaFuncAttributeMaxDynamicSharedMemorySize, GEMM_SMEM);
    cudaFuncSetAttribute(flash_fp16_kernel,
                         cudaFuncAttributeMaxDynamicSharedMemorySize, FLASH_SMEM);

    // 1) fused prep: x convert + 4 weight transposes
    prep_kernel<<<8192, 256>>>(x, wq, wk, wv, wo);

    // 2) fused QKV projections
    gemm_qkv_kernel<<<dim3(DM / GBN, MM / GBM, 3), 256, GEMM_SMEM>>>(bq, bk, bv);

    // 3) attention
    flash_fp16_kernel<<<dim3(SS / 128, BB * HH), 256, FLASH_SMEM>>>();

    // 4) output projection
    gemm_out_kernel<<<dim3(DM / GBN, MM / GBM), 256, GEMM_SMEM>>>(bo, out);
}

// round 13
// speedup vs baseline: 3.9573x; 1.0276x over previous
#include <cuda_runtime.h>
#include <cuda_fp16.h>
#include <math.h>
#include <stdint.h>

#define BB 2
#define HH 16
#define SS 2048
#define DH 64
#define DM 1024
#define MM (BB*SS)   // 4096

// ---------------------------------------------------------------------------
// Scratch (device globals)
// ---------------------------------------------------------------------------
__device__ __align__(256) __half g_xf[(size_t)MM*DM];
__device__ __align__(256) __half g_w4[4][(size_t)DM*DM];  // wq,wk,wv,wo [N,K]
// Q,K fp16 [B,H,S,DH] (Q pre-scaled by 1/8); V fp16 transposed [B,H,DH,S]
__device__ __align__(256) __half g_qf[(size_t)MM*DM];
__device__ __align__(256) __half g_kf[(size_t)MM*DM];
__device__ __align__(256) __half g_vf[(size_t)MM*DM];
// ctx fp16 (flash epilogue), row-major [MM, DM]
__device__ __align__(256) __half g_cf[(size_t)MM*DM];

// ---------------------------------------------------------------------------
// PTX helpers
// ---------------------------------------------------------------------------
__device__ __forceinline__ uint32_t smem_u32(const void* p) {
    uint32_t a;
    asm("{ .reg .u64 t; cvta.to.shared.u64 t, %1; cvt.u32.u64 %0, t; }"
        : "=r"(a) : "l"(p));
    return a;
}
__device__ __forceinline__ void cpa16(uint32_t s, const void* g) {
    asm volatile("cp.async.cg.shared.global [%0], [%1], 16;" :: "r"(s), "l"(g));
}
__device__ __forceinline__ void cpa_commit() {
    asm volatile("cp.async.commit_group;" ::: "memory");
}
__device__ __forceinline__ void ldmx4(uint32_t* r, uint32_t addr) {
    asm volatile("ldmatrix.sync.aligned.m8n8.x4.shared.b16 {%0,%1,%2,%3}, [%4];"
                 : "=r"(r[0]), "=r"(r[1]), "=r"(r[2]), "=r"(r[3]) : "r"(addr));
}
__device__ __forceinline__ void mmaf16(float* c, const uint32_t* a,
                                       uint32_t b0, uint32_t b1) {
    asm volatile(
        "mma.sync.aligned.m16n8k16.row.col.f32.f16.f16.f32 "
        "{%0,%1,%2,%3}, {%4,%5,%6,%7}, {%8,%9}, {%0,%1,%2,%3};"
        : "+f"(c[0]), "+f"(c[1]), "+f"(c[2]), "+f"(c[3])
        : "r"(a[0]), "r"(a[1]), "r"(a[2]), "r"(a[3]), "r"(b0), "r"(b1));
}
__device__ __forceinline__ uint32_t packh(float lo, float hi) {
    __half2 h = __floats2half2_rn(lo, hi);
    return *reinterpret_cast<uint32_t*>(&h);
}

// ---------------------------------------------------------------------------
// Fused prep: blocks [0,4096): x fp32->fp16; [4096,8192): weight transpose.
// ---------------------------------------------------------------------------
__global__ void prep_kernel(const float* __restrict__ x,
                            const float* __restrict__ wq,
                            const float* __restrict__ wk,
                            const float* __restrict__ wv,
                            const float* __restrict__ wo)
{
    int b = blockIdx.x;
    if (b < 4096) {
        int i = (b * 256 + threadIdx.x) * 4;
        float4 v = *(const float4*)(x + i);
        __half2 h0 = __floats2half2_rn(v.x, v.y);
        __half2 h1 = __floats2half2_rn(v.z, v.w);
        ((__half2*)(g_xf + i))[0] = h0;
        ((__half2*)(g_xf + i))[1] = h1;
        return;
    }
    __shared__ float t[32][33];
    int r = b - 4096;
    int w = r >> 10;
    int tl = r & 1023;
    int n0 = (tl & 31) * 32, k0 = (tl >> 5) * 32;
    const float* W = (w == 0) ? wq : (w == 1) ? wk : (w == 2) ? wv : wo;
    __half* T = g_w4[w];
    int tx = threadIdx.x & 31, ty = threadIdx.x >> 5;
    #pragma unroll
    for (int i = 0; i < 32; i += 8)
        t[ty + i][tx] = W[(size_t)(k0 + ty + i) * DM + n0 + tx];
    __syncthreads();
    #pragma unroll
    for (int i = 0; i < 32; i += 8) {
        float v = t[tx][ty + i];
        T[(size_t)(n0 + ty + i) * DM + k0 + tx] = __float2half_rn(v);
    }
}

// ---------------------------------------------------------------------------
// fp16 GEMM core: CTA tile 128x64, 8 warps (4 M x 2 N), warp tile 32x32,
// BK=32, double-buffered cp.async, 3 CTAs/SM (24 warps).
// ---------------------------------------------------------------------------
#define GBM 128
#define GBN 64
#define GBK 32
#define OA_B (128 * 80)       // A tile: 128 rows x 80 B
#define OW_B (64 * 80)        // W tile: 64 rows x 80 B
#define STAGE_B (OA_B + OW_B) // 15360
#define GEMM_SMEM (2 * STAGE_B)  // 30720
#define O_A 0
#define O_W OA_B

struct GemmAcc { float a[2][4][4]; };

__device__ __forceinline__ void gemm_mainloop(const __half* __restrict__ A,
                                              const __half* __restrict__ W,
                                              int bm, int bn, char* smem,
                                              GemmAcc& acc)
{
    const uint32_t sbase = smem_u32(smem);
    const int tid = threadIdx.x;
    const int lane = tid & 31;
    const int wid = tid >> 5;
    const int wm = wid & 3;     // 4 x 32 rows
    const int wn = wid >> 2;    // 2 x 32 cols

    #pragma unroll
    for (int i = 0; i < 2; i++)
        #pragma unroll
        for (int j = 0; j < 4; j++)
            #pragma unroll
            for (int e = 0; e < 4; e++) acc.a[i][j][e] = 0.f;

    const int lr = tid >> 2;        // 0..63
    const int lc = tid & 3;

    auto load_stage = [&](int buf, int k0) {
        uint32_t sb = sbase + buf * STAGE_B;
        size_t g0 = (size_t)(bm + lr) * DM + k0 + lc * 8;
        size_t g1 = (size_t)(bm + 64 + lr) * DM + k0 + lc * 8;
        size_t gw = (size_t)(bn + lr) * DM + k0 + lc * 8;
        cpa16(sb + O_A + lr * 80 + lc * 16, A + g0);
        cpa16(sb + O_A + (64 + lr) * 80 + lc * 16, A + g1);
        cpa16(sb + O_W + lr * 80 + lc * 16, W + gw);
    };

    const int a_row = (lane & 7) + ((lane >> 3) & 1) * 8;
    const int a_kh  = (lane >> 4) * 8;
    const int b_n   = (lane & 7) + ((lane >> 4) & 1) * 8;
    const int b_kh  = ((lane >> 3) & 1) * 8;

    const int T = DM / GBK;
    load_stage(0, 0);
    cpa_commit();

    for (int t = 0; t < T; t++) {
        if (t + 1 < T) {
            load_stage((t + 1) & 1, (t + 1) * GBK);
            cpa_commit();
            asm volatile("cp.async.wait_group 1;" ::: "memory");
        } else {
            asm volatile("cp.async.wait_group 0;" ::: "memory");
        }
        __syncthreads();

        const uint32_t sb = sbase + (t & 1) * STAGE_B;
        #pragma unroll
        for (int ks = 0; ks < 2; ks++) {
            uint32_t af[2][4];
            #pragma unroll
            for (int mi = 0; mi < 2; mi++) {
                uint32_t ra = sb + O_A + (wm * 32 + mi * 16 + a_row) * 80
                            + (ks * 16 + a_kh) * 2;
                ldmx4(af[mi], ra);
            }
            #pragma unroll
            for (int np = 0; np < 2; np++) {
                uint32_t wf[4];
                uint32_t rb = sb + O_W + (wn * 32 + np * 16 + b_n) * 80
                            + (ks * 16 + b_kh) * 2;
                ldmx4(wf, rb);
                #pragma unroll
                for (int mi = 0; mi < 2; mi++) {
                    mmaf16(acc.a[mi][np * 2 + 0], af[mi], wf[0], wf[1]);
                    mmaf16(acc.a[mi][np * 2 + 1], af[mi], wf[2], wf[3]);
                }
            }
        }
        __syncthreads();
    }
}

// Fused QKV projection: blockIdx.z selects weight/bias/output.
// z=0: Q (scaled 0.125) -> [B,H,S,DH]; z=1: K -> [B,H,S,DH];
// z=2: V -> [B,H,DH,S] transposed.
__global__ __launch_bounds__(256, 3)
void gemm_qkv_kernel(const float* __restrict__ bq,
                     const float* __restrict__ bk,
                     const float* __restrict__ bv)
{
    extern __shared__ char smem[];
    const int z = blockIdx.z;
    const int bm = blockIdx.y * GBM;
    const int bn = blockIdx.x * GBN;
    const float* bias = (z == 0) ? bq : (z == 1) ? bk : bv;
    __half* Of = (z == 0) ? g_qf : (z == 1) ? g_kf : g_vf;
    const float qs = (z == 0) ? 0.125f : 1.f;

    GemmAcc acc;
    gemm_mainloop(g_xf, g_w4[z], bm, bn, smem, acc);

    const int lane = threadIdx.x & 31;
    const int wid = threadIdx.x >> 5;
    const int wm = wid & 3;
    const int wn = wid >> 2;

    #pragma unroll
    for (int mi = 0; mi < 2; mi++) {
        #pragma unroll
        for (int nf = 0; nf < 4; nf++) {
            int gcol = bn + wn * 32 + nf * 8 + (lane & 3) * 2;
            float b0 = __ldg(bias + gcol);
            float b1 = __ldg(bias + gcol + 1);
            #pragma unroll
            for (int half = 0; half < 2; half++) {
                int row = bm + wm * 32 + mi * 16 + (lane >> 2) + half * 8;
                float vx = (acc.a[mi][nf][half * 2 + 0] + b0) * qs;
                float vy = (acc.a[mi][nf][half * 2 + 1] + b1) * qs;
                int hh = gcol >> 6, d = gcol & 63;
                int b_ = row >> 11, s = row & 2047;
                if (z != 2) {
                    size_t o = ((((size_t)b_ * HH + hh) * SS + s) * DH) + d;
                    __half2 hv = __floats2half2_rn(vx, vy);
                    *(__half2*)&Of[o] = hv;
                } else {
                    size_t o = ((((size_t)b_ * HH + hh) * DH + d) * SS) + s;
                    Of[o] = __float2half_rn(vx);
                    Of[o + SS] = __float2half_rn(vy);
                }
            }
        }
    }
}

// Output projection: ctx(fp16) @ wo^T + bo -> fp32 out
__global__ __launch_bounds__(256, 3)
void gemm_out_kernel(const float* __restrict__ bias, float* __restrict__ C)
{
    extern __shared__ char smem[];
    const int bm = blockIdx.y * GBM;
    const int bn = blockIdx.x * GBN;

    GemmAcc acc;
    gemm_mainloop(g_cf, g_w4[3], bm, bn, smem, acc);

    const int lane = threadIdx.x & 31;
    const int wid = threadIdx.x >> 5;
    const int wm = wid & 3;
    const int wn = wid >> 2;

    #pragma unroll
    for (int mi = 0; mi < 2; mi++) {
        #pragma unroll
        for (int nf = 0; nf < 4; nf++) {
            int gcol = bn + wn * 32 + nf * 8 + (lane & 3) * 2;
            float b0 = __ldg(bias + gcol);
            float b1 = __ldg(bias + gcol + 1);
            #pragma unroll
            for (int half = 0; half < 2; half++) {
                int row = bm + wm * 32 + mi * 16 + (lane >> 2) + half * 8;
                float2 v;
                v.x = acc.a[mi][nf][half * 2 + 0] + b0;
                v.y = acc.a[mi][nf][half * 2 + 1] + b1;
                *(float2*)&C[(size_t)row * DM + gcol] = v;
            }
        }
    }
}

// ---------------------------------------------------------------------------
// Tensor-core flash attention, fp16 QK and PV, fp32 softmax (unchanged R12).
// ---------------------------------------------------------------------------
#define FQSZ (128 * 144)
#define FKOFF 0
#define FVOFF (64 * 144)
#define FSTAGE (2 * 64 * 144)
#define FLASH_SMEM (FQSZ + 2 * FSTAGE)  // 55296

__global__ __launch_bounds__(256, 2)
void flash_fp16_kernel()
{
    extern __shared__ char smem[];
    const uint32_t sbase = smem_u32(smem);
    const int tid = threadIdx.x;
    const int lane = tid & 31;
    const int wid = tid >> 5;
    const int bh = blockIdx.y;
    const int q0 = blockIdx.x * 128;

    const size_t qbase = ((size_t)bh * SS + q0) * DH;
    const size_t kbase = (size_t)bh * SS * DH;
    const size_t vbase = (size_t)bh * DH * SS;

    #pragma unroll
    for (int i = 0; i < 4; i++) {
        int c = tid + i * 256;
        int row = c >> 3, col = c & 7;
        cpa16(sbase + row * 144 + col * 16,
              g_qf + qbase + (size_t)row * DH + col * 8);
    }
    cpa_commit();

    auto load_kv = [&](int buf, int kv0) {
        uint32_t sb = sbase + FQSZ + buf * FSTAGE;
        #pragma unroll
        for (int i = 0; i < 2; i++) {
            int c = tid + i * 256;
            int row = c >> 3, col = c & 7;
            uint32_t so = row * 144 + col * 16;
            cpa16(sb + FKOFF + so, g_kf + kbase + (size_t)(kv0 + row) * DH + col * 8);
            cpa16(sb + FVOFF + so, g_vf + vbase + (size_t)row * SS + kv0 + col * 8);
        }
    };

    load_kv(0, 0);
    cpa_commit();
    asm volatile("cp.async.wait_group 0;" ::: "memory");
    __syncthreads();

    const int a_row = (lane & 7) + ((lane >> 3) & 1) * 8;
    const int a_kh  = (lane >> 4) * 8;
    const int b_n   = (lane & 7) + ((lane >> 4) & 1) * 8;
    const int b_kh  = ((lane >> 3) & 1) * 8;

    float Oa[8][4];
    #pragma unroll
    for (int j = 0; j < 8; j++)
        #pragma unroll
        for (int e = 0; e < 4; e++) Oa[j][e] = 0.f;
    float m0 = -1e30f, m1 = -1e30f, l0 = 0.f, l1 = 0.f;

    const int T = SS / 64;
    for (int t = 0; t < T; t++) {
        if (t + 1 < T) {
            load_kv((t + 1) & 1, (t + 1) * 64);
            cpa_commit();
            asm volatile("cp.async.wait_group 1;" ::: "memory");
        } else {
            asm volatile("cp.async.wait_group 0;" ::: "memory");
        }
        __syncthreads();

        const uint32_t sb = sbase + FQSZ + (t & 1) * FSTAGE;

        float S[8][4];
        #pragma unroll
        for (int j = 0; j < 8; j++)
            #pragma unroll
            for (int e = 0; e < 4; e++) S[j][e] = 0.f;

        #pragma unroll
        for (int ks = 0; ks < 4; ks++) {
            uint32_t qf4[4];
            ldmx4(qf4, sbase + (wid * 16 + a_row) * 144 + (ks * 16 + a_kh) * 2);
            #pragma unroll
            for (int np = 0; np < 4; np++) {
                uint32_t kf4[4];
                ldmx4(kf4, sb + FKOFF + (np * 16 + b_n) * 144 + (ks * 16 + b_kh) * 2);
                mmaf16(S[np * 2 + 0], qf4, kf4[0], kf4[1]);
                mmaf16(S[np * 2 + 1], qf4, kf4[2], kf4[3]);
            }
        }

        float rx0 = -1e30f, rx1 = -1e30f;
        #pragma unroll
        for (int j = 0; j < 8; j++) {
            rx0 = fmaxf(rx0, fmaxf(S[j][0], S[j][1]));
            rx1 = fmaxf(rx1, fmaxf(S[j][2], S[j][3]));
        }
        rx0 = fmaxf(rx0, __shfl_xor_sync(0xFFFFFFFF, rx0, 1));
        rx0 = fmaxf(rx0, __shfl_xor_sync(0xFFFFFFFF, rx0, 2));
        rx1 = fmaxf(rx1, __shfl_xor_sync(0xFFFFFFFF, rx1, 1));
        rx1 = fmaxf(rx1, __shfl_xor_sync(0xFFFFFFFF, rx1, 2));
        float mn0 = fmaxf(m0, rx0), mn1 = fmaxf(m1, rx1);
        if (mn0 != m0 || mn1 != m1) {
            float al0 = __expf(m0 - mn0), al1 = __expf(m1 - mn1);
            l0 *= al0; l1 *= al1;
            #pragma unroll
            for (int j = 0; j < 8; j++) {
                Oa[j][0] *= al0; Oa[j][1] *= al0;
                Oa[j][2] *= al1; Oa[j][3] *= al1;
            }
            m0 = mn0; m1 = mn1;
        }
        #pragma unroll
        for (int j = 0; j < 8; j++) {
            S[j][0] = __expf(S[j][0] - m0);
            S[j][1] = __expf(S[j][1] - m0);
            S[j][2] = __expf(S[j][2] - m1);
            S[j][3] = __expf(S[j][3] - m1);
            l0 += S[j][0] + S[j][1];
            l1 += S[j][2] + S[j][3];
        }

        #pragma unroll
        for (int kc = 0; kc < 4; kc++) {
            uint32_t pa[4];
            #pragma unroll
            for (int u = 0; u < 2; u++) {
                const float* sp = S[kc * 2 + u];
                pa[u * 2 + 0] = packh(sp[0], sp[1]);
                pa[u * 2 + 1] = packh(sp[2], sp[3]);
            }
            #pragma unroll
            for (int np = 0; np < 4; np++) {
                uint32_t vf4[4];
                ldmx4(vf4, sb + FVOFF + (np * 16 + b_n) * 144 + (kc * 16 + b_kh) * 2);
                mmaf16(Oa[np * 2 + 0], pa, vf4[0], vf4[1]);
                mmaf16(Oa[np * 2 + 1], pa, vf4[2], vf4[3]);
            }
        }
        __syncthreads();
    }

    l0 += __shfl_xor_sync(0xFFFFFFFF, l0, 1);
    l0 += __shfl_xor_sync(0xFFFFFFFF, l0, 2);
    l1 += __shfl_xor_sync(0xFFFFFFFF, l1, 1);
    l1 += __shfl_xor_sync(0xFFFFFFFF, l1, 2);
    float inv0 = 1.f / l0, inv1 = 1.f / l1;

    const int b_ = bh >> 4, h = bh & 15;
    const int r0 = q0 + wid * 16 + (lane >> 2);
    const int col = h * 64 + (lane & 3) * 2;
    #pragma unroll
    for (int nf = 0; nf < 8; nf++) {
        #pragma unroll
        for (int half = 0; half < 2; half++) {
            float inv = half ? inv1 : inv0;
            float vx = Oa[nf][half * 2 + 0] * inv;
            float vy = Oa[nf][half * 2 + 1] * inv;
            size_t o = ((size_t)b_ * SS + r0 + half * 8) * DM + col + nf * 8;
            __half2 hv = __floats2half2_rn(vx, vy);
            *(__half2*)&g_cf[o] = hv;
        }
    }
}

// ---------------------------------------------------------------------------
extern "C" void kernel_launch(void* const* d_in, const int* in_sizes, int n_in,
                              void* d_out, int out_size)
{
    const float* x  = (const float*)d_in[0];
    const float* wq = (const float*)d_in[1];
    const float* bq = (const float*)d_in[2];
    const float* wk = (const float*)d_in[3];
    const float* bk = (const float*)d_in[4];
    const float* wv = (const float*)d_in[5];
    const float* bv = (const float*)d_in[6];
    const float* wo = (const float*)d_in[7];
    const float* bo = (const float*)d_in[8];
    float* out = (float*)d_out;

    cudaFuncSetAttribute(gemm_qkv_kernel,
                         cudaFuncAttributeMaxDynamicSharedMemorySize, GEMM_SMEM);
    cudaFuncSetAttribute(gemm_out_kernel,
                         cudaFuncAttributeMaxDynamicSharedMemorySize, GEMM_SMEM);
    cudaFuncSetAttribute(flash_fp16_kernel,
                         cudaFuncAttributeMaxDynamicSharedMemorySize, FLASH_SMEM);

    // 1) fused prep
    prep_kernel<<<8192, 256>>>(x, wq, wk, wv, wo);

    // 2) fused QKV projections (CTA tile 128x64, 3 CTAs/SM)
    gemm_qkv_kernel<<<dim3(DM / GBN, MM / GBM, 3), 256, GEMM_SMEM>>>(bq, bk, bv);

    // 3) attention
    flash_fp16_kernel<<<dim3(SS / 128, BB * HH), 256, FLASH_SMEM>>>();

    // 4) output projection
    gemm_out_kernel<<<dim3(DM / GBN, MM / GBM), 256, GEMM_SMEM>>>(bo, out);
}